// round 12
// baseline (speedup 1.0000x reference)
#include <cuda_runtime.h>
#include <math_constants.h>
#include <cstdint>

#define BATCH 4
#define SEQL 2048
#define DMODEL 512
#define NHEAD 8
#define HDIM 64
#define BHEADS (BATCH * NHEAD)      // 32
#define NROWS (BATCH * SEQL)        // 8192
#define SCALE 0.125f                // 1/sqrt(64)
#define LN_EPS 1e-5f

// -------------------- device scratch (no allocations allowed) ----------------
__device__ uint32_t g_qh16[BHEADS * SEQL * 32];  // packed half2 pairs along dk
__device__ uint32_t g_kh16[BHEADS * SEQL * 32];
__device__ float    g_vh[BHEADS * SEQL * HDIM];  // fp32 V (head layout)
__device__ uint32_t g_vp[BHEADS * 1024 * 64];    // half2 pairs along token: [bh][kp][dv]
__device__ float    g_ao[BHEADS * SEQL * HDIM];  // attention output, (B,H,L,DV) flat
__device__ float    g_y[NROWS * DMODEL];         // fc output + residual (pre-LN)

// -------------------- helpers ------------------------------------------------
__device__ __forceinline__ uint32_t pack_h2(float lo, float hi) {
    uint32_t r;
    asm("cvt.rn.f16x2.f32 %0, %1, %2;" : "=r"(r) : "f"(hi), "f"(lo));
    return r;
}

__device__ __forceinline__ void mma16(float* c, const uint32_t* a, const uint32_t* b) {
    asm volatile(
        "mma.sync.aligned.m16n8k16.row.col.f32.f16.f16.f32 "
        "{%0,%1,%2,%3}, {%4,%5,%6,%7}, {%8,%9}, {%0,%1,%2,%3};\n"
        : "+f"(c[0]), "+f"(c[1]), "+f"(c[2]), "+f"(c[3])
        : "r"(a[0]), "r"(a[1]), "r"(a[2]), "r"(a[3]), "r"(b[0]), "r"(b[1]));
}

#define CP16(dst_u32, src_ptr) \
    asm volatile("cp.async.cg.shared.global [%0], [%1], 16;\n" :: "r"(dst_u32), "l"(src_ptr))
#define CP_COMMIT() asm volatile("cp.async.commit_group;\n" ::)
#define CP_WAIT1()  asm volatile("cp.async.wait_group 1;\n" ::)
#define CP_WAIT0()  asm volatile("cp.async.wait_group 0;\n" ::)

// ============================================================================
// scores: S = (Q K^T)*SCALE with mask -> attn (fp32). fp16 mma m16n8k16.
// 8 heads of one batch per block; 2-stage double buffer. (R9 verbatim)
// ============================================================================
__global__ __launch_bounds__(256) void scores_mma_kernel(const int* __restrict__ mask,
                                                         float* __restrict__ attn) {
    extern __shared__ uint32_t dynsm32[];           // 2 bufs x (Q 128x20 + K 128x20) u32
    __shared__ uint32_t Ms[512];                    // mask bitmask
    const int b  = blockIdx.z;
    const int q0 = blockIdx.y * 128;
    const int n0 = blockIdx.x * 128;
    const int tid = threadIdx.x, lane = tid & 31, warp = tid >> 5;
    const int wm = (warp >> 2) * 64, wn = (warp & 3) * 32;
    const int lr = tid >> 2;            // 0..63 (row; +64 second half)
    const int c4 = (tid & 3) * 4;       // u32 col 0,4,8,12
    const uint32_t sbase = (uint32_t)__cvta_generic_to_shared(dynsm32);

    const uint32_t* Qbase = g_qh16 + (size_t)(b * NHEAD) * SEQL * 32;
    const uint32_t* Kbase = g_kh16 + (size_t)(b * NHEAD) * SEQL * 32;

    auto issue = [&](int s) {
        int h = s >> 1, kk = (s & 1) * 16;
        int bi = s & 1;
        const uint32_t* Qp = Qbase + (size_t)h * SEQL * 32 + (size_t)(q0 + lr) * 32 + kk + c4;
        const uint32_t* Kp = Kbase + (size_t)h * SEQL * 32 + (size_t)(n0 + lr) * 32 + kk + c4;
        uint32_t qd = sbase + bi * 20480u + (lr * 20 + c4) * 4u;
        uint32_t kd = qd + 10240u;
#pragma unroll
        for (int rr = 0; rr < 128; rr += 64) {
            CP16(qd + rr * 80u, Qp + (size_t)rr * 32);
            CP16(kd + rr * 80u, Kp + (size_t)rr * 32);
        }
        CP_COMMIT();
    };

    // pack mask bitmask (head-invariant)
    {
        const int* mrow = mask + (size_t)b * SEQL * SEQL;
        for (int w = warp; w < 512; w += 8) {
            int row = w >> 2, cg = w & 3;
            int m = mrow[(size_t)(q0 + row) * SEQL + n0 + cg * 32 + lane];
            unsigned bits = __ballot_sync(0xffffffffu, m == 1);
            if (lane == 0) Ms[w] = bits;
        }
    }

    issue(0);
    issue(1);

    float acc[4][4][4] = {};

    for (int s = 0; s < 16; s++) {
        if (s == 15) { CP_WAIT0(); } else { CP_WAIT1(); }
        __syncthreads();

        const int bi = s & 1;
        const uint32_t* Qb = dynsm32 + bi * 5120;
        const uint32_t* Kb = Qb + 2560;
#pragma unroll
        for (int g = 0; g < 2; g++) {               // two k16 groups per 32-dk slab
            const int kp0 = g * 8 + (lane & 3);
            uint32_t af[4][4], bf[4][2];
#pragma unroll
            for (int tm = 0; tm < 4; tm++) {
                int r0 = wm + tm * 16 + (lane >> 2);
                af[tm][0] = Qb[r0 * 20 + kp0];       af[tm][1] = Qb[(r0 + 8) * 20 + kp0];
                af[tm][2] = Qb[r0 * 20 + kp0 + 4];   af[tm][3] = Qb[(r0 + 8) * 20 + kp0 + 4];
            }
#pragma unroll
            for (int tn = 0; tn < 4; tn++) {
                int rn = wn + tn * 8 + (lane >> 2);
                bf[tn][0] = Kb[rn * 20 + kp0]; bf[tn][1] = Kb[rn * 20 + kp0 + 4];
            }
#pragma unroll
            for (int tm = 0; tm < 4; tm++)
#pragma unroll
                for (int tn = 0; tn < 4; tn++) mma16(acc[tm][tn], af[tm], bf[tn]);
        }

        __syncthreads();                    // buffer s&1 free for re-issue
        if (s + 2 < 16) issue(s + 2);

        if (s & 1) {
            int h = s >> 1;
            float* ap = attn + (size_t)(b * NHEAD + h) * SEQL * SEQL;
#pragma unroll
            for (int tm = 0; tm < 4; tm++) {
#pragma unroll
                for (int half = 0; half < 2; half++) {
                    int rl = wm + tm * 16 + (lane >> 2) + half * 8;
#pragma unroll
                    for (int tn = 0; tn < 4; tn++) {
                        int cl = wn + tn * 8 + (lane & 3) * 2;
                        unsigned bits = Ms[rl * 4 + (cl >> 5)];
                        int bit = cl & 31;
                        float s0 = acc[tm][tn][half * 2 + 0] * SCALE;
                        float s1 = acc[tm][tn][half * 2 + 1] * SCALE;
                        if ((bits >> bit) & 1u) s0 = -1e9f;
                        if ((bits >> (bit + 1)) & 1u) s1 = -1e9f;
                        *(float2*)&ap[(size_t)(q0 + rl) * SEQL + n0 + cl] = make_float2(s0, s1);
                    }
                }
            }
#pragma unroll
            for (int tm = 0; tm < 4; tm++)
#pragma unroll
                for (int tn = 0; tn < 4; tn++)
#pragma unroll
                    for (int i = 0; i < 4; i++) acc[tm][tn][i] = 0.f;
        }
    }
}

// ============================================================================
// row softmax in place (memory-bound), float4 I/O (R9 verbatim)
// ============================================================================
__global__ void softmax_kernel(float* __restrict__ attn) {
    const size_t row = blockIdx.x;
    float4* p4 = (float4*)(attn + row * SEQL);
    const int tid = threadIdx.x;
    __shared__ float red[8];
    float4 x0 = p4[tid], x1 = p4[tid + 256];
    float v[8] = {x0.x, x0.y, x0.z, x0.w, x1.x, x1.y, x1.z, x1.w};
    float m = -CUDART_INF_F;
#pragma unroll
    for (int i = 0; i < 8; i++) m = fmaxf(m, v[i]);
#pragma unroll
    for (int o = 16; o > 0; o >>= 1) m = fmaxf(m, __shfl_xor_sync(0xffffffffu, m, o));
    if ((tid & 31) == 0) red[tid >> 5] = m;
    __syncthreads();
    m = red[0];
#pragma unroll
    for (int i = 1; i < 8; i++) m = fmaxf(m, red[i]);
    __syncthreads();
    float s = 0.f;
#pragma unroll
    for (int i = 0; i < 8; i++) { v[i] = __expf(v[i] - m); s += v[i]; }
#pragma unroll
    for (int o = 16; o > 0; o >>= 1) s += __shfl_xor_sync(0xffffffffu, s, o);
    if ((tid & 31) == 0) red[tid >> 5] = s;
    __syncthreads();
    s = 0.f;
#pragma unroll
    for (int i = 0; i < 8; i++) s += red[i];
    float inv = 1.f / s;
    p4[tid]       = make_float4(v[0] * inv, v[1] * inv, v[2] * inv, v[3] * inv);
    p4[tid + 256] = make_float4(v[4] * inv, v[5] * inv, v[6] * inv, v[7] * inv);
}

// ============================================================================
// repack V: fp32 head-layout -> half2 pairs along token. [bh][kp][dv]
// ============================================================================
__global__ void vrepack_kernel() {
    int t = blockIdx.x * 256 + threadIdx.x;        // < 32*1024*64
    int n  = t & 63;
    int kp = (t >> 6) & 1023;
    int bh = t >> 16;
    size_t base = ((size_t)bh * SEQL + 2 * kp) * HDIM + n;
    g_vp[t] = pack_h2(g_vh[base], g_vh[base + HDIM]);
}

// ============================================================================
// PV: out = attn @ V, fp16 mma m16n8k16. (R9 verbatim)
// ============================================================================
__global__ __launch_bounds__(256, 2) void pv_mma_kernel(const float* __restrict__ attn) {
    extern __shared__ float dynsm[];    // 2 bufs x (A 128x36 f32 | Vp 16x72 u32)
    const int bh = blockIdx.y;
    const int q0 = blockIdx.x * 128;
    const float* Ap = attn + (size_t)bh * SEQL * SEQL;
    const uint32_t* Vpg = g_vp + (size_t)bh * 1024 * 64;
    const int tid = threadIdx.x, lane = tid & 31, warp = tid >> 5;
    const int wm = warp * 16;
    const int pr = tid >> 3, pc = (tid & 7) * 4;    // A tile loader
    const int vkp = tid >> 4, vnc = (tid & 15) * 4; // V tile loader (u32)
    const uint32_t sbase = (uint32_t)__cvta_generic_to_shared(dynsm);

    auto issue = [&](int s) {
        int bi = s & 1;
        uint32_t ad = sbase + bi * 23040u + (pr * 36 + pc) * 4u;
        uint32_t vd = sbase + bi * 23040u + 18432u + (vkp * 72 + vnc) * 4u;
        const float* ag = Ap + (size_t)(q0 + pr) * SEQL + s * 32 + pc;
#pragma unroll
        for (int rr = 0; rr < 128; rr += 32) CP16(ad + rr * 144u, ag + (size_t)rr * SEQL);
        const uint32_t* vg = Vpg + (size_t)(s * 16 + vkp) * 64 + vnc;
        CP16(vd, vg);
        CP_COMMIT();
    };

    issue(0);
    issue(1);

    float acc[8][4] = {};
    const int r0 = wm + (lane >> 2);

    for (int s = 0; s < 64; s++) {
        if (s == 63) { CP_WAIT0(); } else { CP_WAIT1(); }
        __syncthreads();

        const int bi = s & 1;
        const float* Ab = dynsm + bi * 5760;
        const uint32_t* Vb = (const uint32_t*)(Ab + 4608);
#pragma unroll
        for (int g = 0; g < 2; g++) {
            const int ka = g * 16 + (lane & 3) * 2;
            const int kb = g * 8 + (lane & 3);
            uint32_t af[4], bf[8][2];
            {
                float2 a0 = *(const float2*)&Ab[r0 * 36 + ka];
                float2 a1 = *(const float2*)&Ab[(r0 + 8) * 36 + ka];
                float2 a2 = *(const float2*)&Ab[r0 * 36 + ka + 8];
                float2 a3 = *(const float2*)&Ab[(r0 + 8) * 36 + ka + 8];
                af[0] = pack_h2(a0.x, a0.y);
                af[1] = pack_h2(a1.x, a1.y);
                af[2] = pack_h2(a2.x, a2.y);
                af[3] = pack_h2(a3.x, a3.y);
            }
#pragma unroll
            for (int tn = 0; tn < 8; tn++) {
                int cn = tn * 8 + (lane >> 2);
                bf[tn][0] = Vb[kb * 72 + cn];
                bf[tn][1] = Vb[(kb + 4) * 72 + cn];
            }
#pragma unroll
            for (int tn = 0; tn < 8; tn++) mma16(acc[tn], af, bf[tn]);
        }

        __syncthreads();
        if (s + 2 < 64) issue(s + 2);
    }

#pragma unroll
    for (int half = 0; half < 2; half++) {
        int row = q0 + wm + (lane >> 2) + half * 8;
#pragma unroll
        for (int tn = 0; tn < 8; tn++) {
            int col = tn * 8 + (lane & 3) * 2;
            *(float2*)&g_ao[((size_t)bh * SEQL + row) * HDIM + col] =
                make_float2(acc[tn][half * 2 + 0], acc[tn][half * 2 + 1]);
        }
    }
}

// ============================================================================
// proj: all three projections in one launch (grid.z selects q/k/v).
// NOW fp16 mma16 mainloop: inputs packed to half2 (pairs along k) in smem.
// q/k outputs packed half2; v fp32.
// ============================================================================
__global__ void proj_mma_kernel(const float* __restrict__ q,
                                const float* __restrict__ k,
                                const float* __restrict__ v,
                                const float* __restrict__ wq_w,
                                const float* __restrict__ wq_b,
                                const float* __restrict__ wv_w,
                                const float* __restrict__ wv_b,
                                uint32_t* __restrict__ oq16,
                                uint32_t* __restrict__ ok16,
                                float* __restrict__ ov) {
    const int which = blockIdx.z;
    const float* A    = which == 0 ? q : (which == 1 ? k : v);
    const float* W    = which == 2 ? wv_w : wq_w;      // faithful bug: k uses wq
    const float* bias = which == 2 ? wv_b : wq_b;

    __shared__ uint32_t As[128][20];   // 16 data u32 (32 halves) + 4 pad
    __shared__ uint32_t Ws[128][20];
    const int n0 = blockIdx.y * 128;
    const int j0 = blockIdx.x * 128;
    const int tid = threadIdx.x, lane = tid & 31, warp = tid >> 5;
    const int wm = (warp >> 2) * 64, wn = (warp & 3) * 32;
    float acc[4][4][4] = {};
    const int lr = tid >> 2;           // 0..63 (rows lr, lr+64)
    const int c4 = (tid & 3) * 4;      // u32 cols c4..c4+3  (fp32 cols c4*2..c4*2+7)

    for (int ks = 0; ks < DMODEL / 32; ks++) {
#pragma unroll
        for (int rr = 0; rr < 128; rr += 64) {
            const float* ap = &A[(size_t)(n0 + lr + rr) * DMODEL + ks * 32 + c4 * 2];
            float4 a0 = *(const float4*)ap;
            float4 a1 = *(const float4*)(ap + 4);
            As[lr + rr][c4 + 0] = pack_h2(a0.x, a0.y);
            As[lr + rr][c4 + 1] = pack_h2(a0.z, a0.w);
            As[lr + rr][c4 + 2] = pack_h2(a1.x, a1.y);
            As[lr + rr][c4 + 3] = pack_h2(a1.z, a1.w);
            const float* wp = &W[(size_t)(j0 + lr + rr) * DMODEL + ks * 32 + c4 * 2];
            float4 w0 = *(const float4*)wp;
            float4 w1 = *(const float4*)(wp + 4);
            Ws[lr + rr][c4 + 0] = pack_h2(w0.x, w0.y);
            Ws[lr + rr][c4 + 1] = pack_h2(w0.z, w0.w);
            Ws[lr + rr][c4 + 2] = pack_h2(w1.x, w1.y);
            Ws[lr + rr][c4 + 3] = pack_h2(w1.z, w1.w);
        }
        __syncthreads();
#pragma unroll
        for (int g = 0; g < 2; g++) {
            const int kp0 = g * 8 + (lane & 3);
            uint32_t af[4][4], bf[4][2];
#pragma unroll
            for (int tm = 0; tm < 4; tm++) {
                int r0 = wm + tm * 16 + (lane >> 2);
                af[tm][0] = As[r0][kp0];       af[tm][1] = As[r0 + 8][kp0];
                af[tm][2] = As[r0][kp0 + 4];   af[tm][3] = As[r0 + 8][kp0 + 4];
            }
#pragma unroll
            for (int tn = 0; tn < 4; tn++) {
                int rn = wn + tn * 8 + (lane >> 2);
                bf[tn][0] = Ws[rn][kp0]; bf[tn][1] = Ws[rn][kp0 + 4];
            }
#pragma unroll
            for (int tm = 0; tm < 4; tm++)
#pragma unroll
                for (int tn = 0; tn < 4; tn++) mma16(acc[tm][tn], af[tm], bf[tn]);
        }
        __syncthreads();
    }

#pragma unroll
    for (int tm = 0; tm < 4; tm++) {
#pragma unroll
        for (int half = 0; half < 2; half++) {
            int n = n0 + wm + tm * 16 + (lane >> 2) + half * 8;
            int b = n >> 11, l = n & (SEQL - 1);
#pragma unroll
            for (int tn = 0; tn < 4; tn++) {
                int col = j0 + wn + tn * 8 + (lane & 3) * 2;
                int h = col >> 6, dk = col & 63;
                float2 bv = *(const float2*)&bias[col];
                float v0 = acc[tm][tn][half * 2 + 0] + bv.x;
                float v1 = acc[tm][tn][half * 2 + 1] + bv.y;
                size_t rowbase = (size_t)(b * NHEAD + h) * SEQL + l;
                if (which == 2) {
                    *(float2*)&ov[rowbase * HDIM + dk] = make_float2(v0, v1);
                } else {
                    uint32_t* o16 = which == 0 ? oq16 : ok16;
                    o16[rowbase * 32 + (dk >> 1)] = pack_h2(v0, v1);
                }
            }
        }
    }
}

// ============================================================================
// fc: y = x @ fc_w^T + fc_b + residual, faithful .view() permutation fused.
// NOW fp16 mma16 mainloop (same packing as proj).
// ============================================================================
__global__ void fc_mma_kernel(const float* __restrict__ W,
                              const float* __restrict__ bias,
                              const float* __restrict__ resid) {
    __shared__ uint32_t As[128][20];
    __shared__ uint32_t Ws[128][20];
    const int n0 = blockIdx.y * 128;
    const int j0 = blockIdx.x * 128;
    const int tid = threadIdx.x, lane = tid & 31, warp = tid >> 5;
    const int wm = (warp >> 2) * 64, wn = (warp & 3) * 32;
    float acc[4][4][4] = {};
    const int lr = tid >> 2;           // 0..63
    const int c4 = (tid & 3) * 4;      // u32 cols; fp32 col base = c4*2

    for (int ks = 0; ks < DMODEL / 32; ks++) {
#pragma unroll
        for (int rr = 0; rr < 128; rr += 64) {
            // faithful buffer reinterpretation gather (8 contiguous fp32)
            int n = n0 + lr + rr;
            int c = ks * 32 + c4 * 2;
            int bb = n >> 11, l = n & 2047;
            int h2 = 2 * bb + ((l >> 10) & 1);
            int l3 = (l & 1023) * 2 + (c >> 8);
            int b2 = (c >> 6) & 3;
            int d  = c & 63;
            size_t f = (size_t)h2 * 524288 + (size_t)b2 * 131072 + (size_t)l3 * 64 + d;
            float4 a0 = *(const float4*)&g_ao[f];
            float4 a1 = *(const float4*)&g_ao[f + 4];
            As[lr + rr][c4 + 0] = pack_h2(a0.x, a0.y);
            As[lr + rr][c4 + 1] = pack_h2(a0.z, a0.w);
            As[lr + rr][c4 + 2] = pack_h2(a1.x, a1.y);
            As[lr + rr][c4 + 3] = pack_h2(a1.z, a1.w);
            const float* wp = &W[(size_t)(j0 + lr + rr) * DMODEL + ks * 32 + c4 * 2];
            float4 w0 = *(const float4*)wp;
            float4 w1 = *(const float4*)(wp + 4);
            Ws[lr + rr][c4 + 0] = pack_h2(w0.x, w0.y);
            Ws[lr + rr][c4 + 1] = pack_h2(w0.z, w0.w);
            Ws[lr + rr][c4 + 2] = pack_h2(w1.x, w1.y);
            Ws[lr + rr][c4 + 3] = pack_h2(w1.z, w1.w);
        }
        __syncthreads();
#pragma unroll
        for (int g = 0; g < 2; g++) {
            const int kp0 = g * 8 + (lane & 3);
            uint32_t af[4][4], bf[4][2];
#pragma unroll
            for (int tm = 0; tm < 4; tm++) {
                int r0 = wm + tm * 16 + (lane >> 2);
                af[tm][0] = As[r0][kp0];       af[tm][1] = As[r0 + 8][kp0];
                af[tm][2] = As[r0][kp0 + 4];   af[tm][3] = As[r0 + 8][kp0 + 4];
            }
#pragma unroll
            for (int tn = 0; tn < 4; tn++) {
                int rn = wn + tn * 8 + (lane >> 2);
                bf[tn][0] = Ws[rn][kp0]; bf[tn][1] = Ws[rn][kp0 + 4];
            }
#pragma unroll
            for (int tm = 0; tm < 4; tm++)
#pragma unroll
                for (int tn = 0; tn < 4; tn++) mma16(acc[tm][tn], af[tm], bf[tn]);
        }
        __syncthreads();
    }

#pragma unroll
    for (int tm = 0; tm < 4; tm++) {
#pragma unroll
        for (int half = 0; half < 2; half++) {
            int n = n0 + wm + tm * 16 + (lane >> 2) + half * 8;
#pragma unroll
            for (int tn = 0; tn < 4; tn++) {
                int col = j0 + wn + tn * 8 + (lane & 3) * 2;
                float2 bv = *(const float2*)&bias[col];
                float2 rv = *(const float2*)&resid[(size_t)n * DMODEL + col];
                float v0 = acc[tm][tn][half * 2 + 0] + bv.x + rv.x;
                float v1 = acc[tm][tn][half * 2 + 1] + bv.y + rv.y;
                *(float2*)&g_y[(size_t)n * DMODEL + col] = make_float2(v0, v1);
            }
        }
    }
}

// -------------------- layernorm ---------------------------------------------
__global__ void ln_kernel(const float* __restrict__ gam,
                          const float* __restrict__ bet,
                          float* __restrict__ y) {
    const int n = blockIdx.x;
    const float* px = g_y + (size_t)n * DMODEL;
    const int tid = threadIdx.x;
    __shared__ float red[4];
    float v[4];
    float s = 0.f;
#pragma unroll
    for (int i = 0; i < 4; i++) { v[i] = px[tid + i * 128]; s += v[i]; }
#pragma unroll
    for (int o = 16; o > 0; o >>= 1) s += __shfl_xor_sync(0xffffffffu, s, o);
    if ((tid & 31) == 0) red[tid >> 5] = s;
    __syncthreads();
    float mu = (red[0] + red[1] + red[2] + red[3]) * (1.0f / DMODEL);
    __syncthreads();
    float vs = 0.f;
#pragma unroll
    for (int i = 0; i < 4; i++) { float d = v[i] - mu; vs += d * d; }
#pragma unroll
    for (int o = 16; o > 0; o >>= 1) vs += __shfl_xor_sync(0xffffffffu, vs, o);
    if ((tid & 31) == 0) red[tid >> 5] = vs;
    __syncthreads();
    float var = (red[0] + red[1] + red[2] + red[3]) * (1.0f / DMODEL);
    float inv = rsqrtf(var + LN_EPS);
#pragma unroll
    for (int i = 0; i < 4; i++) {
        int c = tid + i * 128;
        y[(size_t)n * DMODEL + c] = (v[i] - mu) * inv * gam[c] + bet[c];
    }
}

// ============================================================================
extern "C" void kernel_launch(void* const* d_in, const int* in_sizes, int n_in,
                              void* d_out, int out_size) {
    const float* q    = (const float*)d_in[0];
    const float* k    = (const float*)d_in[1];
    const float* v    = (const float*)d_in[2];
    const int*   mask = (const int*)d_in[3];
    const float* wq_w = (const float*)d_in[4];
    const float* wq_b = (const float*)d_in[5];
    const float* wv_w = (const float*)d_in[6];
    const float* wv_b = (const float*)d_in[7];
    const float* fc_w = (const float*)d_in[8];
    const float* fc_b = (const float*)d_in[9];
    const float* ln_g = (const float*)d_in[10];
    const float* ln_b = (const float*)d_in[11];

    float* y_out    = (float*)d_out;
    float* attn_out = (float*)d_out + (size_t)NROWS * DMODEL;

    uint32_t *p_qh16, *p_kh16;
    float *p_vh;
    cudaGetSymbolAddress((void**)&p_qh16, g_qh16);
    cudaGetSymbolAddress((void**)&p_kh16, g_kh16);
    cudaGetSymbolAddress((void**)&p_vh, g_vh);

    static bool attrs_set = false;
    if (!attrs_set) {
        cudaFuncSetAttribute(scores_mma_kernel,
                             cudaFuncAttributeMaxDynamicSharedMemorySize, 40960);
        cudaFuncSetAttribute(pv_mma_kernel,
                             cudaFuncAttributeMaxDynamicSharedMemorySize, 46080);
        attrs_set = true;
    }

    dim3 gProj(DMODEL / 128, NROWS / 128, 3);    // (4, 64, 3)
    proj_mma_kernel<<<gProj, 256>>>(q, k, v, wq_w, wq_b, wv_w, wv_b,
                                    p_qh16, p_kh16, p_vh);

    vrepack_kernel<<<(BHEADS * 1024 * 64) / 256, 256>>>();

    dim3 gScores(SEQL / 128, SEQL / 128, BATCH);  // (16, 16, 4)
    scores_mma_kernel<<<gScores, 256, 40960>>>(mask, attn_out);

    softmax_kernel<<<BHEADS * SEQL, 256>>>(attn_out);

    dim3 gPV(SEQL / 128, BHEADS);   // (16, 32)
    pv_mma_kernel<<<gPV, 256, 46080>>>(attn_out);

    dim3 gFc(DMODEL / 128, NROWS / 128);
    fc_mma_kernel<<<gFc, 256>>>(fc_w, fc_b, q);

    ln_kernel<<<NROWS, 128>>>(ln_g, ln_b, y_out);
}

// round 14
// speedup vs baseline: 1.2739x; 1.2739x over previous
#include <cuda_runtime.h>
#include <math_constants.h>
#include <cstdint>

#define BATCH 4
#define SEQL 2048
#define DMODEL 512
#define NHEAD 8
#define HDIM 64
#define BHEADS (BATCH * NHEAD)      // 32
#define NROWS (BATCH * SEQL)        // 8192
#define SCALE 0.125f                // 1/sqrt(64)
#define LN_EPS 1e-5f

// -------------------- device scratch (no allocations allowed) ----------------
__device__ uint32_t g_qh16[BHEADS * SEQL * 32];  // packed half2 pairs along dk
__device__ uint32_t g_kh16[BHEADS * SEQL * 32];
__device__ float    g_vh[BHEADS * SEQL * HDIM];  // fp32 V (head layout)
__device__ uint32_t g_vp[BHEADS * 1024 * 64];    // half2 pairs along token: [bh][kp][dv]
__device__ float    g_ao[BHEADS * SEQL * HDIM];  // attention output, (B,H,L,DV) flat
__device__ float    g_y[NROWS * DMODEL];         // fc output + residual (pre-LN)

// -------------------- helpers ------------------------------------------------
__device__ __forceinline__ uint32_t f2tf(float x) {
    uint32_t r;
    asm("cvt.rna.tf32.f32 %0, %1;" : "=r"(r) : "f"(x));
    return r;
}

__device__ __forceinline__ uint32_t pack_h2(float lo, float hi) {
    uint32_t r;
    asm("cvt.rn.f16x2.f32 %0, %1, %2;" : "=r"(r) : "f"(hi), "f"(lo));
    return r;
}

__device__ __forceinline__ void mma8(float* c, const uint32_t* a, const uint32_t* b) {
    asm volatile(
        "mma.sync.aligned.m16n8k8.row.col.f32.tf32.tf32.f32 "
        "{%0,%1,%2,%3}, {%4,%5,%6,%7}, {%8,%9}, {%0,%1,%2,%3};\n"
        : "+f"(c[0]), "+f"(c[1]), "+f"(c[2]), "+f"(c[3])
        : "r"(a[0]), "r"(a[1]), "r"(a[2]), "r"(a[3]), "r"(b[0]), "r"(b[1]));
}

__device__ __forceinline__ void mma16(float* c, const uint32_t* a, const uint32_t* b) {
    asm volatile(
        "mma.sync.aligned.m16n8k16.row.col.f32.f16.f16.f32 "
        "{%0,%1,%2,%3}, {%4,%5,%6,%7}, {%8,%9}, {%0,%1,%2,%3};\n"
        : "+f"(c[0]), "+f"(c[1]), "+f"(c[2]), "+f"(c[3])
        : "r"(a[0]), "r"(a[1]), "r"(a[2]), "r"(a[3]), "r"(b[0]), "r"(b[1]));
}

#define CP16(dst_u32, src_ptr) \
    asm volatile("cp.async.cg.shared.global [%0], [%1], 16;\n" :: "r"(dst_u32), "l"(src_ptr))
#define CP_COMMIT() asm volatile("cp.async.commit_group;\n" ::)
#define CP_WAIT1()  asm volatile("cp.async.wait_group 1;\n" ::)
#define CP_WAIT0()  asm volatile("cp.async.wait_group 0;\n" ::)

// ============================================================================
// scores: S = (Q K^T)*SCALE with mask -> attn (fp32). fp16 mma m16n8k16.
// 8 heads of one batch per block; 2-stage double buffer.
// ============================================================================
__global__ __launch_bounds__(256) void scores_mma_kernel(const int* __restrict__ mask,
                                                         float* __restrict__ attn) {
    extern __shared__ uint32_t dynsm32[];           // 2 bufs x (Q 128x20 + K 128x20) u32
    __shared__ uint32_t Ms[512];                    // mask bitmask
    const int b  = blockIdx.z;
    const int q0 = blockIdx.y * 128;
    const int n0 = blockIdx.x * 128;
    const int tid = threadIdx.x, lane = tid & 31, warp = tid >> 5;
    const int wm = (warp >> 2) * 64, wn = (warp & 3) * 32;
    const int lr = tid >> 2;            // 0..63 (row; +64 second half)
    const int c4 = (tid & 3) * 4;       // u32 col 0,4,8,12
    const uint32_t sbase = (uint32_t)__cvta_generic_to_shared(dynsm32);

    const uint32_t* Qbase = g_qh16 + (size_t)(b * NHEAD) * SEQL * 32;
    const uint32_t* Kbase = g_kh16 + (size_t)(b * NHEAD) * SEQL * 32;

    auto issue = [&](int s) {
        int h = s >> 1, kk = (s & 1) * 16;
        int bi = s & 1;
        const uint32_t* Qp = Qbase + (size_t)h * SEQL * 32 + (size_t)(q0 + lr) * 32 + kk + c4;
        const uint32_t* Kp = Kbase + (size_t)h * SEQL * 32 + (size_t)(n0 + lr) * 32 + kk + c4;
        uint32_t qd = sbase + bi * 20480u + (lr * 20 + c4) * 4u;
        uint32_t kd = qd + 10240u;
#pragma unroll
        for (int rr = 0; rr < 128; rr += 64) {
            CP16(qd + rr * 80u, Qp + (size_t)rr * 32);
            CP16(kd + rr * 80u, Kp + (size_t)rr * 32);
        }
        CP_COMMIT();
    };

    // pack mask bitmask (head-invariant)
    {
        const int* mrow = mask + (size_t)b * SEQL * SEQL;
        for (int w = warp; w < 512; w += 8) {
            int row = w >> 2, cg = w & 3;
            int m = mrow[(size_t)(q0 + row) * SEQL + n0 + cg * 32 + lane];
            unsigned bits = __ballot_sync(0xffffffffu, m == 1);
            if (lane == 0) Ms[w] = bits;
        }
    }

    issue(0);
    issue(1);

    float acc[4][4][4] = {};

    for (int s = 0; s < 16; s++) {
        if (s == 15) { CP_WAIT0(); } else { CP_WAIT1(); }
        __syncthreads();

        const int bi = s & 1;
        const uint32_t* Qb = dynsm32 + bi * 5120;
        const uint32_t* Kb = Qb + 2560;
#pragma unroll
        for (int g = 0; g < 2; g++) {               // two k16 groups per 32-dk slab
            const int kp0 = g * 8 + (lane & 3);
            uint32_t af[4][4], bf[4][2];
#pragma unroll
            for (int tm = 0; tm < 4; tm++) {
                int r0 = wm + tm * 16 + (lane >> 2);
                af[tm][0] = Qb[r0 * 20 + kp0];       af[tm][1] = Qb[(r0 + 8) * 20 + kp0];
                af[tm][2] = Qb[r0 * 20 + kp0 + 4];   af[tm][3] = Qb[(r0 + 8) * 20 + kp0 + 4];
            }
#pragma unroll
            for (int tn = 0; tn < 4; tn++) {
                int rn = wn + tn * 8 + (lane >> 2);
                bf[tn][0] = Kb[rn * 20 + kp0]; bf[tn][1] = Kb[rn * 20 + kp0 + 4];
            }
#pragma unroll
            for (int tm = 0; tm < 4; tm++)
#pragma unroll
                for (int tn = 0; tn < 4; tn++) mma16(acc[tm][tn], af[tm], bf[tn]);
        }

        __syncthreads();                    // buffer s&1 free for re-issue
        if (s + 2 < 16) issue(s + 2);

        if (s & 1) {
            int h = s >> 1;
            float* ap = attn + (size_t)(b * NHEAD + h) * SEQL * SEQL;
#pragma unroll
            for (int tm = 0; tm < 4; tm++) {
#pragma unroll
                for (int half = 0; half < 2; half++) {
                    int rl = wm + tm * 16 + (lane >> 2) + half * 8;
#pragma unroll
                    for (int tn = 0; tn < 4; tn++) {
                        int cl = wn + tn * 8 + (lane & 3) * 2;
                        unsigned bits = Ms[rl * 4 + (cl >> 5)];
                        int bit = cl & 31;
                        float s0 = acc[tm][tn][half * 2 + 0] * SCALE;
                        float s1 = acc[tm][tn][half * 2 + 1] * SCALE;
                        if ((bits >> bit) & 1u) s0 = -1e9f;
                        if ((bits >> (bit + 1)) & 1u) s1 = -1e9f;
                        *(float2*)&ap[(size_t)(q0 + rl) * SEQL + n0 + cl] = make_float2(s0, s1);
                    }
                }
            }
#pragma unroll
            for (int tm = 0; tm < 4; tm++)
#pragma unroll
                for (int tn = 0; tn < 4; tn++)
#pragma unroll
                    for (int i = 0; i < 4; i++) acc[tm][tn][i] = 0.f;
        }
    }
}

// ============================================================================
// row softmax in place (memory-bound), float4 I/O
// ============================================================================
__global__ void softmax_kernel(float* __restrict__ attn) {
    const size_t row = blockIdx.x;
    float4* p4 = (float4*)(attn + row * SEQL);
    const int tid = threadIdx.x;
    __shared__ float red[8];
    float4 x0 = p4[tid], x1 = p4[tid + 256];
    float v[8] = {x0.x, x0.y, x0.z, x0.w, x1.x, x1.y, x1.z, x1.w};
    float m = -CUDART_INF_F;
#pragma unroll
    for (int i = 0; i < 8; i++) m = fmaxf(m, v[i]);
#pragma unroll
    for (int o = 16; o > 0; o >>= 1) m = fmaxf(m, __shfl_xor_sync(0xffffffffu, m, o));
    if ((tid & 31) == 0) red[tid >> 5] = m;
    __syncthreads();
    m = red[0];
#pragma unroll
    for (int i = 1; i < 8; i++) m = fmaxf(m, red[i]);
    __syncthreads();
    float s = 0.f;
#pragma unroll
    for (int i = 0; i < 8; i++) { v[i] = __expf(v[i] - m); s += v[i]; }
#pragma unroll
    for (int o = 16; o > 0; o >>= 1) s += __shfl_xor_sync(0xffffffffu, s, o);
    if ((tid & 31) == 0) red[tid >> 5] = s;
    __syncthreads();
    s = 0.f;
#pragma unroll
    for (int i = 0; i < 8; i++) s += red[i];
    float inv = 1.f / s;
    p4[tid]       = make_float4(v[0] * inv, v[1] * inv, v[2] * inv, v[3] * inv);
    p4[tid + 256] = make_float4(v[4] * inv, v[5] * inv, v[6] * inv, v[7] * inv);
}

// ============================================================================
// repack V: fp32 head-layout -> half2 pairs along token. [bh][kp][dv]
// ============================================================================
__global__ void vrepack_kernel() {
    int t = blockIdx.x * 256 + threadIdx.x;        // < 32*1024*64
    int n  = t & 63;
    int kp = (t >> 6) & 1023;
    int bh = t >> 16;
    size_t base = ((size_t)bh * SEQL + 2 * kp) * HDIM + n;
    g_vp[t] = pack_h2(g_vh[base], g_vh[base + HDIM]);
}

// ============================================================================
// PV: out = attn @ V, fp16 mma m16n8k16. attn fp32 (converted in fragment
// gather); V pre-packed half2 token pairs. 2-stage cp.async.
// ============================================================================
__global__ __launch_bounds__(256, 2) void pv_mma_kernel(const float* __restrict__ attn) {
    extern __shared__ float dynsm[];    // 2 bufs x (A 128x36 f32 | Vp 16x72 u32)
    const int bh = blockIdx.y;
    const int q0 = blockIdx.x * 128;
    const float* Ap = attn + (size_t)bh * SEQL * SEQL;
    const uint32_t* Vpg = g_vp + (size_t)bh * 1024 * 64;
    const int tid = threadIdx.x, lane = tid & 31, warp = tid >> 5;
    const int wm = warp * 16;
    const int pr = tid >> 3, pc = (tid & 7) * 4;    // A tile loader
    const int vkp = tid >> 4, vnc = (tid & 15) * 4; // V tile loader (u32)
    const uint32_t sbase = (uint32_t)__cvta_generic_to_shared(dynsm);

    auto issue = [&](int s) {
        int bi = s & 1;
        uint32_t ad = sbase + bi * 23040u + (pr * 36 + pc) * 4u;
        uint32_t vd = sbase + bi * 23040u + 18432u + (vkp * 72 + vnc) * 4u;
        const float* ag = Ap + (size_t)(q0 + pr) * SEQL + s * 32 + pc;
#pragma unroll
        for (int rr = 0; rr < 128; rr += 32) CP16(ad + rr * 144u, ag + (size_t)rr * SEQL);
        const uint32_t* vg = Vpg + (size_t)(s * 16 + vkp) * 64 + vnc;
        CP16(vd, vg);
        CP_COMMIT();
    };

    issue(0);
    issue(1);

    float acc[8][4] = {};
    const int r0 = wm + (lane >> 2);

    for (int s = 0; s < 64; s++) {
        if (s == 63) { CP_WAIT0(); } else { CP_WAIT1(); }
        __syncthreads();

        const int bi = s & 1;
        const float* Ab = dynsm + bi * 5760;
        const uint32_t* Vb = (const uint32_t*)(Ab + 4608);
#pragma unroll
        for (int g = 0; g < 2; g++) {
            const int ka = g * 16 + (lane & 3) * 2;
            const int kb = g * 8 + (lane & 3);
            uint32_t af[4], bf[8][2];
            {
                float2 a0 = *(const float2*)&Ab[r0 * 36 + ka];
                float2 a1 = *(const float2*)&Ab[(r0 + 8) * 36 + ka];
                float2 a2 = *(const float2*)&Ab[r0 * 36 + ka + 8];
                float2 a3 = *(const float2*)&Ab[(r0 + 8) * 36 + ka + 8];
                af[0] = pack_h2(a0.x, a0.y);
                af[1] = pack_h2(a1.x, a1.y);
                af[2] = pack_h2(a2.x, a2.y);
                af[3] = pack_h2(a3.x, a3.y);
            }
#pragma unroll
            for (int tn = 0; tn < 8; tn++) {
                int cn = tn * 8 + (lane >> 2);
                bf[tn][0] = Vb[kb * 72 + cn];
                bf[tn][1] = Vb[(kb + 4) * 72 + cn];
            }
#pragma unroll
            for (int tn = 0; tn < 8; tn++) mma16(acc[tn], af, bf[tn]);
        }

        __syncthreads();
        if (s + 2 < 64) issue(s + 2);
    }

#pragma unroll
    for (int half = 0; half < 2; half++) {
        int row = q0 + wm + (lane >> 2) + half * 8;
#pragma unroll
        for (int tn = 0; tn < 8; tn++) {
            int col = tn * 8 + (lane & 3) * 2;
            *(float2*)&g_ao[((size_t)bh * SEQL + row) * HDIM + col] =
                make_float2(acc[tn][half * 2 + 0], acc[tn][half * 2 + 1]);
        }
    }
}

// ============================================================================
// proj: all three projections in one launch (grid.z selects q/k/v).
// q/k write packed half2 (pairs along dk); v writes fp32.  tf32 mainloop.
// ============================================================================
__global__ void proj_mma_kernel(const float* __restrict__ q,
                                const float* __restrict__ k,
                                const float* __restrict__ v,
                                const float* __restrict__ wq_w,
                                const float* __restrict__ wq_b,
                                const float* __restrict__ wv_w,
                                const float* __restrict__ wv_b,
                                uint32_t* __restrict__ oq16,
                                uint32_t* __restrict__ ok16,
                                float* __restrict__ ov) {
    const int which = blockIdx.z;
    const float* A    = which == 0 ? q : (which == 1 ? k : v);
    const float* W    = which == 2 ? wv_w : wq_w;      // faithful bug: k uses wq
    const float* bias = which == 2 ? wv_b : wq_b;

    __shared__ uint32_t As[128][36];
    __shared__ uint32_t Ws[128][36];
    const int n0 = blockIdx.y * 128;
    const int j0 = blockIdx.x * 128;
    const int tid = threadIdx.x, lane = tid & 31, warp = tid >> 5;
    const int wm = (warp >> 2) * 64, wn = (warp & 3) * 32;
    float acc[4][4][4] = {};
    const int lr = tid >> 3;
    const int lc = (tid & 7) * 4;

    for (int ks = 0; ks < DMODEL / 32; ks++) {
#pragma unroll
        for (int rr = 0; rr < 128; rr += 32) {
            float4 av = *(const float4*)&A[(size_t)(n0 + lr + rr) * DMODEL + ks * 32 + lc];
            As[lr + rr][lc + 0] = f2tf(av.x); As[lr + rr][lc + 1] = f2tf(av.y);
            As[lr + rr][lc + 2] = f2tf(av.z); As[lr + rr][lc + 3] = f2tf(av.w);
            float4 wv = *(const float4*)&W[(size_t)(j0 + lr + rr) * DMODEL + ks * 32 + lc];
            Ws[lr + rr][lc + 0] = f2tf(wv.x); Ws[lr + rr][lc + 1] = f2tf(wv.y);
            Ws[lr + rr][lc + 2] = f2tf(wv.z); Ws[lr + rr][lc + 3] = f2tf(wv.w);
        }
        __syncthreads();
#pragma unroll
        for (int k8 = 0; k8 < 4; k8++) {
            const int c0 = k8 * 8 + (lane & 3);
            uint32_t af[4][4], bf[4][2];
#pragma unroll
            for (int tm = 0; tm < 4; tm++) {
                int r0 = wm + tm * 16 + (lane >> 2);
                af[tm][0] = As[r0][c0];     af[tm][1] = As[r0 + 8][c0];
                af[tm][2] = As[r0][c0 + 4]; af[tm][3] = As[r0 + 8][c0 + 4];
            }
#pragma unroll
            for (int tn = 0; tn < 4; tn++) {
                int rn = wn + tn * 8 + (lane >> 2);
                bf[tn][0] = Ws[rn][c0]; bf[tn][1] = Ws[rn][c0 + 4];
            }
#pragma unroll
            for (int tm = 0; tm < 4; tm++)
#pragma unroll
                for (int tn = 0; tn < 4; tn++) mma8(acc[tm][tn], af[tm], bf[tn]);
        }
        __syncthreads();
    }

#pragma unroll
    for (int tm = 0; tm < 4; tm++) {
#pragma unroll
        for (int half = 0; half < 2; half++) {
            int n = n0 + wm + tm * 16 + (lane >> 2) + half * 8;
            int b = n >> 11, l = n & (SEQL - 1);
#pragma unroll
            for (int tn = 0; tn < 4; tn++) {
                int col = j0 + wn + tn * 8 + (lane & 3) * 2;
                int h = col >> 6, dk = col & 63;
                float2 bv = *(const float2*)&bias[col];
                float v0 = acc[tm][tn][half * 2 + 0] + bv.x;
                float v1 = acc[tm][tn][half * 2 + 1] + bv.y;
                size_t rowbase = (size_t)(b * NHEAD + h) * SEQL + l;
                if (which == 2) {
                    *(float2*)&ov[rowbase * HDIM + dk] = make_float2(v0, v1);
                } else {
                    uint32_t* o16 = which == 0 ? oq16 : ok16;
                    o16[rowbase * 32 + (dk >> 1)] = pack_h2(v0, v1);
                }
            }
        }
    }
}

// ============================================================================
// fc: y = x @ fc_w^T + fc_b + residual, faithful .view() permutation fused.
// ============================================================================
__global__ void fc_mma_kernel(const float* __restrict__ W,
                              const float* __restrict__ bias,
                              const float* __restrict__ resid) {
    __shared__ uint32_t As[128][36];
    __shared__ uint32_t Ws[128][36];
    const int n0 = blockIdx.y * 128;
    const int j0 = blockIdx.x * 128;
    const int tid = threadIdx.x, lane = tid & 31, warp = tid >> 5;
    const int wm = (warp >> 2) * 64, wn = (warp & 3) * 32;
    float acc[4][4][4] = {};
    const int lr = tid >> 3;
    const int lc = (tid & 7) * 4;

    for (int ks = 0; ks < DMODEL / 32; ks++) {
#pragma unroll
        for (int rr = 0; rr < 128; rr += 32) {
            int n = n0 + lr + rr;
            int c = ks * 32 + lc;
            int bb = n >> 11, l = n & 2047;
            int h2 = 2 * bb + ((l >> 10) & 1);
            int l3 = (l & 1023) * 2 + (c >> 8);
            int b2 = (c >> 6) & 3;
            int d  = c & 63;
            size_t f = (size_t)h2 * 524288 + (size_t)b2 * 131072 + (size_t)l3 * 64 + d;
            float4 av = *(const float4*)&g_ao[f];
            As[lr + rr][lc + 0] = f2tf(av.x); As[lr + rr][lc + 1] = f2tf(av.y);
            As[lr + rr][lc + 2] = f2tf(av.z); As[lr + rr][lc + 3] = f2tf(av.w);
            float4 wv = *(const float4*)&W[(size_t)(j0 + lr + rr) * DMODEL + ks * 32 + lc];
            Ws[lr + rr][lc + 0] = f2tf(wv.x); Ws[lr + rr][lc + 1] = f2tf(wv.y);
            Ws[lr + rr][lc + 2] = f2tf(wv.z); Ws[lr + rr][lc + 3] = f2tf(wv.w);
        }
        __syncthreads();
#pragma unroll
        for (int k8 = 0; k8 < 4; k8++) {
            const int c0 = k8 * 8 + (lane & 3);
            uint32_t af[4][4], bf[4][2];
#pragma unroll
            for (int tm = 0; tm < 4; tm++) {
                int r0 = wm + tm * 16 + (lane >> 2);
                af[tm][0] = As[r0][c0];     af[tm][1] = As[r0 + 8][c0];
                af[tm][2] = As[r0][c0 + 4]; af[tm][3] = As[r0 + 8][c0 + 4];
            }
#pragma unroll
            for (int tn = 0; tn < 4; tn++) {
                int rn = wn + tn * 8 + (lane >> 2);
                bf[tn][0] = Ws[rn][c0]; bf[tn][1] = Ws[rn][c0 + 4];
            }
#pragma unroll
            for (int tm = 0; tm < 4; tm++)
#pragma unroll
                for (int tn = 0; tn < 4; tn++) mma8(acc[tm][tn], af[tm], bf[tn]);
        }
        __syncthreads();
    }

#pragma unroll
    for (int tm = 0; tm < 4; tm++) {
#pragma unroll
        for (int half = 0; half < 2; half++) {
            int n = n0 + wm + tm * 16 + (lane >> 2) + half * 8;
#pragma unroll
            for (int tn = 0; tn < 4; tn++) {
                int col = j0 + wn + tn * 8 + (lane & 3) * 2;
                float2 bv = *(const float2*)&bias[col];
                float2 rv = *(const float2*)&resid[(size_t)n * DMODEL + col];
                float v0 = acc[tm][tn][half * 2 + 0] + bv.x + rv.x;
                float v1 = acc[tm][tn][half * 2 + 1] + bv.y + rv.y;
                *(float2*)&g_y[(size_t)n * DMODEL + col] = make_float2(v0, v1);
            }
        }
    }
}

// -------------------- layernorm ---------------------------------------------
__global__ void ln_kernel(const float* __restrict__ gam,
                          const float* __restrict__ bet,
                          float* __restrict__ y) {
    const int n = blockIdx.x;
    const float* px = g_y + (size_t)n * DMODEL;
    const int tid = threadIdx.x;
    __shared__ float red[4];
    float v[4];
    float s = 0.f;
#pragma unroll
    for (int i = 0; i < 4; i++) { v[i] = px[tid + i * 128]; s += v[i]; }
#pragma unroll
    for (int o = 16; o > 0; o >>= 1) s += __shfl_xor_sync(0xffffffffu, s, o);
    if ((tid & 31) == 0) red[tid >> 5] = s;
    __syncthreads();
    float mu = (red[0] + red[1] + red[2] + red[3]) * (1.0f / DMODEL);
    __syncthreads();
    float vs = 0.f;
#pragma unroll
    for (int i = 0; i < 4; i++) { float d = v[i] - mu; vs += d * d; }
#pragma unroll
    for (int o = 16; o > 0; o >>= 1) vs += __shfl_xor_sync(0xffffffffu, vs, o);
    if ((tid & 31) == 0) red[tid >> 5] = vs;
    __syncthreads();
    float var = (red[0] + red[1] + red[2] + red[3]) * (1.0f / DMODEL);
    float inv = rsqrtf(var + LN_EPS);
#pragma unroll
    for (int i = 0; i < 4; i++) {
        int c = tid + i * 128;
        y[(size_t)n * DMODEL + c] = (v[i] - mu) * inv * gam[c] + bet[c];
    }
}

// ============================================================================
extern "C" void kernel_launch(void* const* d_in, const int* in_sizes, int n_in,
                              void* d_out, int out_size) {
    const float* q    = (const float*)d_in[0];
    const float* k    = (const float*)d_in[1];
    const float* v    = (const float*)d_in[2];
    const int*   mask = (const int*)d_in[3];
    const float* wq_w = (const float*)d_in[4];
    const float* wq_b = (const float*)d_in[5];
    const float* wv_w = (const float*)d_in[6];
    const float* wv_b = (const float*)d_in[7];
    const float* fc_w = (const float*)d_in[8];
    const float* fc_b = (const float*)d_in[9];
    const float* ln_g = (const float*)d_in[10];
    const float* ln_b = (const float*)d_in[11];

    float* y_out    = (float*)d_out;
    float* attn_out = (float*)d_out + (size_t)NROWS * DMODEL;

    uint32_t *p_qh16, *p_kh16;
    float *p_vh;
    cudaGetSymbolAddress((void**)&p_qh16, g_qh16);
    cudaGetSymbolAddress((void**)&p_kh16, g_kh16);
    cudaGetSymbolAddress((void**)&p_vh, g_vh);

    static bool attrs_set = false;
    if (!attrs_set) {
        cudaFuncSetAttribute(scores_mma_kernel,
                             cudaFuncAttributeMaxDynamicSharedMemorySize, 40960);
        cudaFuncSetAttribute(pv_mma_kernel,
                             cudaFuncAttributeMaxDynamicSharedMemorySize, 46080);
        attrs_set = true;
    }

    dim3 gProj(DMODEL / 128, NROWS / 128, 3);    // (4, 64, 3)
    proj_mma_kernel<<<gProj, 256>>>(q, k, v, wq_w, wq_b, wv_w, wv_b,
                                    p_qh16, p_kh16, p_vh);

    vrepack_kernel<<<(BHEADS * 1024 * 64) / 256, 256>>>();

    dim3 gScores(SEQL / 128, SEQL / 128, BATCH);  // (16, 16, 4)
    scores_mma_kernel<<<gScores, 256, 40960>>>(mask, attn_out);

    softmax_kernel<<<BHEADS * SEQL, 256>>>(attn_out);

    dim3 gPV(SEQL / 128, BHEADS);   // (16, 32)
    pv_mma_kernel<<<gPV, 256, 46080>>>(attn_out);

    dim3 gFc(DMODEL / 128, NROWS / 128);
    fc_mma_kernel<<<gFc, 256>>>(fc_w, fc_b, q);

    ln_kernel<<<NROWS, 128>>>(ln_g, ln_b, y_out);
}

// round 15
// speedup vs baseline: 1.3332x; 1.0466x over previous
#include <cuda_runtime.h>
#include <math_constants.h>
#include <cstdint>

#define BATCH 4
#define SEQL 2048
#define DMODEL 512
#define NHEAD 8
#define HDIM 64
#define BHEADS (BATCH * NHEAD)      // 32
#define NROWS (BATCH * SEQL)        // 8192
#define SCALE 0.125f                // 1/sqrt(64)
#define LN_EPS 1e-5f

// -------------------- device scratch (no allocations allowed) ----------------
__device__ uint32_t g_qh16[BHEADS * SEQL * 32];  // packed half2 pairs along dk
__device__ uint32_t g_kh16[BHEADS * SEQL * 32];
__device__ float    g_vh[BHEADS * SEQL * HDIM];  // fp32 V (head layout)
__device__ uint32_t g_vp[BHEADS * 1024 * 64];    // half2 pairs along token: [bh][kp][dv]
__device__ float    g_ao[BHEADS * SEQL * HDIM];  // attention output, (B,H,L,DV) flat
__device__ float    g_y[NROWS * DMODEL];         // fc output + residual (pre-LN)
__device__ float    g_ps[BHEADS * SEQL * 16];    // per-(row, k-tile) sum of exp(s)
__device__ float    g_inv[BHEADS * SEQL];        // 1 / row sumexp

// -------------------- helpers ------------------------------------------------
__device__ __forceinline__ uint32_t f2tf(float x) {
    uint32_t r;
    asm("cvt.rna.tf32.f32 %0, %1;" : "=r"(r) : "f"(x));
    return r;
}

__device__ __forceinline__ uint32_t pack_h2(float lo, float hi) {
    uint32_t r;
    asm("cvt.rn.f16x2.f32 %0, %1, %2;" : "=r"(r) : "f"(hi), "f"(lo));
    return r;
}

__device__ __forceinline__ void mma8(float* c, const uint32_t* a, const uint32_t* b) {
    asm volatile(
        "mma.sync.aligned.m16n8k8.row.col.f32.tf32.tf32.f32 "
        "{%0,%1,%2,%3}, {%4,%5,%6,%7}, {%8,%9}, {%0,%1,%2,%3};\n"
        : "+f"(c[0]), "+f"(c[1]), "+f"(c[2]), "+f"(c[3])
        : "r"(a[0]), "r"(a[1]), "r"(a[2]), "r"(a[3]), "r"(b[0]), "r"(b[1]));
}

__device__ __forceinline__ void mma16(float* c, const uint32_t* a, const uint32_t* b) {
    asm volatile(
        "mma.sync.aligned.m16n8k16.row.col.f32.f16.f16.f32 "
        "{%0,%1,%2,%3}, {%4,%5,%6,%7}, {%8,%9}, {%0,%1,%2,%3};\n"
        : "+f"(c[0]), "+f"(c[1]), "+f"(c[2]), "+f"(c[3])
        : "r"(a[0]), "r"(a[1]), "r"(a[2]), "r"(a[3]), "r"(b[0]), "r"(b[1]));
}

#define CP16(dst_u32, src_ptr) \
    asm volatile("cp.async.cg.shared.global [%0], [%1], 16;\n" :: "r"(dst_u32), "l"(src_ptr))
#define CP_COMMIT() asm volatile("cp.async.commit_group;\n" ::)
#define CP_WAIT1()  asm volatile("cp.async.wait_group 1;\n" ::)
#define CP_WAIT0()  asm volatile("cp.async.wait_group 0;\n" ::)

// ============================================================================
// scores: raw S=(QK^T)*SCALE masked -> attn (fp32), PLUS per-(row, k-tile)
// sum of exp(s) partials (no max needed: |s| small; masked exp(-1e9)=0).
// fp16 mma m16n8k16; 8 heads per block; 2-stage double buffer.
// ============================================================================
__global__ __launch_bounds__(256) void scores_mma_kernel(const int* __restrict__ mask,
                                                         float* __restrict__ attn) {
    extern __shared__ uint32_t dynsm32[];           // 2 bufs x (Q 128x20 + K 128x20) u32
    __shared__ uint32_t Ms[512];                    // mask bitmask
    __shared__ float sm_e[128][4];                  // per-row per-warpcol sumexp
    const int b  = blockIdx.z;
    const int q0 = blockIdx.y * 128;
    const int n0 = blockIdx.x * 128;
    const int tid = threadIdx.x, lane = tid & 31, warp = tid >> 5;
    const int wm = (warp >> 2) * 64, wn = (warp & 3) * 32;
    const int lr = tid >> 2;            // 0..63 (row; +64 second half)
    const int c4 = (tid & 3) * 4;       // u32 col 0,4,8,12
    const uint32_t sbase = (uint32_t)__cvta_generic_to_shared(dynsm32);

    const uint32_t* Qbase = g_qh16 + (size_t)(b * NHEAD) * SEQL * 32;
    const uint32_t* Kbase = g_kh16 + (size_t)(b * NHEAD) * SEQL * 32;

    auto issue = [&](int s) {
        int h = s >> 1, kk = (s & 1) * 16;
        int bi = s & 1;
        const uint32_t* Qp = Qbase + (size_t)h * SEQL * 32 + (size_t)(q0 + lr) * 32 + kk + c4;
        const uint32_t* Kp = Kbase + (size_t)h * SEQL * 32 + (size_t)(n0 + lr) * 32 + kk + c4;
        uint32_t qd = sbase + bi * 20480u + (lr * 20 + c4) * 4u;
        uint32_t kd = qd + 10240u;
#pragma unroll
        for (int rr = 0; rr < 128; rr += 64) {
            CP16(qd + rr * 80u, Qp + (size_t)rr * 32);
            CP16(kd + rr * 80u, Kp + (size_t)rr * 32);
        }
        CP_COMMIT();
    };

    // pack mask bitmask (head-invariant)
    {
        const int* mrow = mask + (size_t)b * SEQL * SEQL;
        for (int w = warp; w < 512; w += 8) {
            int row = w >> 2, cg = w & 3;
            int m = mrow[(size_t)(q0 + row) * SEQL + n0 + cg * 32 + lane];
            unsigned bits = __ballot_sync(0xffffffffu, m == 1);
            if (lane == 0) Ms[w] = bits;
        }
    }

    issue(0);
    issue(1);

    float acc[4][4][4] = {};

    for (int s = 0; s < 16; s++) {
        if (s == 15) { CP_WAIT0(); } else { CP_WAIT1(); }
        __syncthreads();

        const int bi = s & 1;
        const uint32_t* Qb = dynsm32 + bi * 5120;
        const uint32_t* Kb = Qb + 2560;
#pragma unroll
        for (int g = 0; g < 2; g++) {               // two k16 groups per 32-dk slab
            const int kp0 = g * 8 + (lane & 3);
            uint32_t af[4][4], bf[4][2];
#pragma unroll
            for (int tm = 0; tm < 4; tm++) {
                int r0 = wm + tm * 16 + (lane >> 2);
                af[tm][0] = Qb[r0 * 20 + kp0];       af[tm][1] = Qb[(r0 + 8) * 20 + kp0];
                af[tm][2] = Qb[r0 * 20 + kp0 + 4];   af[tm][3] = Qb[(r0 + 8) * 20 + kp0 + 4];
            }
#pragma unroll
            for (int tn = 0; tn < 4; tn++) {
                int rn = wn + tn * 8 + (lane >> 2);
                bf[tn][0] = Kb[rn * 20 + kp0]; bf[tn][1] = Kb[rn * 20 + kp0 + 4];
            }
#pragma unroll
            for (int tm = 0; tm < 4; tm++)
#pragma unroll
                for (int tn = 0; tn < 4; tn++) mma16(acc[tm][tn], af[tm], bf[tn]);
        }

        __syncthreads();                    // buffer s&1 free for re-issue
        if (s + 2 < 16) issue(s + 2);

        if (s & 1) {
            int h = s >> 1;
            float* ap = attn + (size_t)(b * NHEAD + h) * SEQL * SEQL;
#pragma unroll
            for (int tm = 0; tm < 4; tm++) {
#pragma unroll
                for (int half = 0; half < 2; half++) {
                    int rl = wm + tm * 16 + (lane >> 2) + half * 8;
                    float rs = 0.f;
#pragma unroll
                    for (int tn = 0; tn < 4; tn++) {
                        int cl = wn + tn * 8 + (lane & 3) * 2;
                        unsigned bits = Ms[rl * 4 + (cl >> 5)];
                        int bit = cl & 31;
                        float s0 = acc[tm][tn][half * 2 + 0] * SCALE;
                        float s1 = acc[tm][tn][half * 2 + 1] * SCALE;
                        if ((bits >> bit) & 1u) s0 = -1e9f;
                        if ((bits >> (bit + 1)) & 1u) s1 = -1e9f;
                        rs += __expf(s0) + __expf(s1);     // exp(-1e9) = 0 exactly
                        *(float2*)&ap[(size_t)(q0 + rl) * SEQL + n0 + cl] = make_float2(s0, s1);
                    }
                    // quad reduce (lanes sharing lane>>2 hold the same row)
                    rs += __shfl_xor_sync(0xffffffffu, rs, 1);
                    rs += __shfl_xor_sync(0xffffffffu, rs, 2);
                    if ((lane & 3) == 0) sm_e[rl][warp & 3] = rs;
                }
            }
            __syncthreads();
            if (tid < 128) {
                float et = sm_e[tid][0] + sm_e[tid][1] + sm_e[tid][2] + sm_e[tid][3];
                size_t ridx = (size_t)(b * NHEAD + h) * SEQL + q0 + tid;
                g_ps[ridx * 16 + blockIdx.x] = et;
            }
#pragma unroll
            for (int tm = 0; tm < 4; tm++)
#pragma unroll
                for (int tn = 0; tn < 4; tn++)
#pragma unroll
                    for (int i = 0; i < 4; i++) acc[tm][tn][i] = 0.f;
        }
    }
}

// ============================================================================
// reduce: merge 16 k-tile partial sums per row -> inv = 1/S
// ============================================================================
__global__ void reduce_kernel() {
    int row = blockIdx.x * 256 + threadIdx.x;      // < 65536
    float S = 0.f;
#pragma unroll
    for (int t = 0; t < 16; t++) S += g_ps[(size_t)row * 16 + t];
    g_inv[row] = 1.f / S;
}

// ============================================================================
// repack V: fp32 head-layout -> half2 pairs along token. [bh][kp][dv]
// ============================================================================
__global__ void vrepack_kernel() {
    int t = blockIdx.x * 256 + threadIdx.x;        // < 32*1024*64
    int n  = t & 63;
    int kp = (t >> 6) & 1023;
    int bh = t >> 16;
    size_t base = ((size_t)bh * SEQL + 2 * kp) * HDIM + n;
    g_vp[t] = pack_h2(g_vh[base], g_vh[base + HDIM]);
}

// ============================================================================
// PV fused with softmax finalize: reads RAW S tiles, p = exp(s)*inv applied
// ONCE per element IN the mma fragment gather (fragments tile the operand
// exactly once), the same registers are stored as the final fp32 attn and
// packed fp16 for the mma. No extra barriers, no extra smem stage.
// ============================================================================
__global__ __launch_bounds__(256, 2) void pv_mma_kernel(float* __restrict__ attn) {
    extern __shared__ float dynsm[];    // 2 bufs x (S 128x36 f32 | Vp 16x72 u32)
    __shared__ float sI[128];
    const int bh = blockIdx.y;
    const int q0 = blockIdx.x * 128;
    float* Ap = attn + (size_t)bh * SEQL * SEQL;
    const uint32_t* Vpg = g_vp + (size_t)bh * 1024 * 64;
    const int tid = threadIdx.x, lane = tid & 31, warp = tid >> 5;
    const int wm = warp * 16;
    const int pr = tid >> 3, pc = (tid & 7) * 4;    // S tile loader
    const int vkp = tid >> 4, vnc = (tid & 15) * 4; // V tile loader (u32)
    const uint32_t sbase = (uint32_t)__cvta_generic_to_shared(dynsm);

    if (tid < 128) sI[tid] = g_inv[(size_t)bh * SEQL + q0 + tid];

    auto issue = [&](int s) {
        int bi = s & 1;
        uint32_t ad = sbase + bi * 23040u + (pr * 36 + pc) * 4u;
        uint32_t vd = sbase + bi * 23040u + 18432u + (vkp * 72 + vnc) * 4u;
        const float* ag = Ap + (size_t)(q0 + pr) * SEQL + s * 32 + pc;
#pragma unroll
        for (int rr = 0; rr < 128; rr += 32) CP16(ad + rr * 144u, ag + (size_t)rr * SEQL);
        const uint32_t* vg = Vpg + (size_t)(s * 16 + vkp) * 64 + vnc;
        CP16(vd, vg);
        CP_COMMIT();
    };

    issue(0);
    issue(1);

    float acc[8][4] = {};
    const int r0 = wm + (lane >> 2);
    float I0 = 0.f, I1 = 0.f;

    for (int s = 0; s < 64; s++) {
        if (s == 63) { CP_WAIT0(); } else { CP_WAIT1(); }
        __syncthreads();
        if (s == 0) { I0 = sI[r0]; I1 = sI[r0 + 8]; }

        const int bi = s & 1;
        const float* Ab = dynsm + bi * 5760;
        const uint32_t* Vb = (const uint32_t*)(Ab + 4608);
        float* arow0 = Ap + (size_t)(q0 + r0) * SEQL + s * 32;
        float* arow1 = Ap + (size_t)(q0 + r0 + 8) * SEQL + s * 32;
#pragma unroll
        for (int g = 0; g < 2; g++) {
            const int ka = g * 16 + (lane & 3) * 2;
            const int kb = g * 8 + (lane & 3);
            uint32_t af[4], bf[8][2];
            {
                float2 a0 = *(const float2*)&Ab[r0 * 36 + ka];
                float2 a1 = *(const float2*)&Ab[(r0 + 8) * 36 + ka];
                float2 a2 = *(const float2*)&Ab[r0 * 36 + ka + 8];
                float2 a3 = *(const float2*)&Ab[(r0 + 8) * 36 + ka + 8];
                float p00 = __expf(a0.x) * I0, p01 = __expf(a0.y) * I0;
                float p10 = __expf(a1.x) * I1, p11 = __expf(a1.y) * I1;
                float p20 = __expf(a2.x) * I0, p21 = __expf(a2.y) * I0;
                float p30 = __expf(a3.x) * I1, p31 = __expf(a3.y) * I1;
                af[0] = pack_h2(p00, p01);
                af[1] = pack_h2(p10, p11);
                af[2] = pack_h2(p20, p21);
                af[3] = pack_h2(p30, p31);
                *(float2*)&arow0[ka]     = make_float2(p00, p01);
                *(float2*)&arow1[ka]     = make_float2(p10, p11);
                *(float2*)&arow0[ka + 8] = make_float2(p20, p21);
                *(float2*)&arow1[ka + 8] = make_float2(p30, p31);
            }
#pragma unroll
            for (int tn = 0; tn < 8; tn++) {
                int cn = tn * 8 + (lane >> 2);
                bf[tn][0] = Vb[kb * 72 + cn];
                bf[tn][1] = Vb[(kb + 4) * 72 + cn];
            }
#pragma unroll
            for (int tn = 0; tn < 8; tn++) mma16(acc[tn], af, bf[tn]);
        }

        __syncthreads();
        if (s + 2 < 64) issue(s + 2);
    }

#pragma unroll
    for (int half = 0; half < 2; half++) {
        int row = q0 + wm + (lane >> 2) + half * 8;
#pragma unroll
        for (int tn = 0; tn < 8; tn++) {
            int col = tn * 8 + (lane & 3) * 2;
            *(float2*)&g_ao[((size_t)bh * SEQL + row) * HDIM + col] =
                make_float2(acc[tn][half * 2 + 0], acc[tn][half * 2 + 1]);
        }
    }
}

// ============================================================================
// proj: all three projections in one launch (grid.z selects q/k/v).
// q/k write packed half2 (pairs along dk); v writes fp32.  tf32 mainloop.
// ============================================================================
__global__ void proj_mma_kernel(const float* __restrict__ q,
                                const float* __restrict__ k,
                                const float* __restrict__ v,
                                const float* __restrict__ wq_w,
                                const float* __restrict__ wq_b,
                                const float* __restrict__ wv_w,
                                const float* __restrict__ wv_b,
                                uint32_t* __restrict__ oq16,
                                uint32_t* __restrict__ ok16,
                                float* __restrict__ ov) {
    const int which = blockIdx.z;
    const float* A    = which == 0 ? q : (which == 1 ? k : v);
    const float* W    = which == 2 ? wv_w : wq_w;      // faithful bug: k uses wq
    const float* bias = which == 2 ? wv_b : wq_b;

    __shared__ uint32_t As[128][36];
    __shared__ uint32_t Ws[128][36];
    const int n0 = blockIdx.y * 128;
    const int j0 = blockIdx.x * 128;
    const int tid = threadIdx.x, lane = tid & 31, warp = tid >> 5;
    const int wm = (warp >> 2) * 64, wn = (warp & 3) * 32;
    float acc[4][4][4] = {};
    const int lr = tid >> 3;
    const int lc = (tid & 7) * 4;

    for (int ks = 0; ks < DMODEL / 32; ks++) {
#pragma unroll
        for (int rr = 0; rr < 128; rr += 32) {
            float4 av = *(const float4*)&A[(size_t)(n0 + lr + rr) * DMODEL + ks * 32 + lc];
            As[lr + rr][lc + 0] = f2tf(av.x); As[lr + rr][lc + 1] = f2tf(av.y);
            As[lr + rr][lc + 2] = f2tf(av.z); As[lr + rr][lc + 3] = f2tf(av.w);
            float4 wv = *(const float4*)&W[(size_t)(j0 + lr + rr) * DMODEL + ks * 32 + lc];
            Ws[lr + rr][lc + 0] = f2tf(wv.x); Ws[lr + rr][lc + 1] = f2tf(wv.y);
            Ws[lr + rr][lc + 2] = f2tf(wv.z); Ws[lr + rr][lc + 3] = f2tf(wv.w);
        }
        __syncthreads();
#pragma unroll
        for (int k8 = 0; k8 < 4; k8++) {
            const int c0 = k8 * 8 + (lane & 3);
            uint32_t af[4][4], bf[4][2];
#pragma unroll
            for (int tm = 0; tm < 4; tm++) {
                int r0 = wm + tm * 16 + (lane >> 2);
                af[tm][0] = As[r0][c0];     af[tm][1] = As[r0 + 8][c0];
                af[tm][2] = As[r0][c0 + 4]; af[tm][3] = As[r0 + 8][c0 + 4];
            }
#pragma unroll
            for (int tn = 0; tn < 4; tn++) {
                int rn = wn + tn * 8 + (lane >> 2);
                bf[tn][0] = Ws[rn][c0]; bf[tn][1] = Ws[rn][c0 + 4];
            }
#pragma unroll
            for (int tm = 0; tm < 4; tm++)
#pragma unroll
                for (int tn = 0; tn < 4; tn++) mma8(acc[tm][tn], af[tm], bf[tn]);
        }
        __syncthreads();
    }

#pragma unroll
    for (int tm = 0; tm < 4; tm++) {
#pragma unroll
        for (int half = 0; half < 2; half++) {
            int n = n0 + wm + tm * 16 + (lane >> 2) + half * 8;
            int b = n >> 11, l = n & (SEQL - 1);
#pragma unroll
            for (int tn = 0; tn < 4; tn++) {
                int col = j0 + wn + tn * 8 + (lane & 3) * 2;
                int h = col >> 6, dk = col & 63;
                float2 bv = *(const float2*)&bias[col];
                float v0 = acc[tm][tn][half * 2 + 0] + bv.x;
                float v1 = acc[tm][tn][half * 2 + 1] + bv.y;
                size_t rowbase = (size_t)(b * NHEAD + h) * SEQL + l;
                if (which == 2) {
                    *(float2*)&ov[rowbase * HDIM + dk] = make_float2(v0, v1);
                } else {
                    uint32_t* o16 = which == 0 ? oq16 : ok16;
                    o16[rowbase * 32 + (dk >> 1)] = pack_h2(v0, v1);
                }
            }
        }
    }
}

// ============================================================================
// fc: y = x @ fc_w^T + fc_b + residual, faithful .view() permutation fused.
// ============================================================================
__global__ void fc_mma_kernel(const float* __restrict__ W,
                              const float* __restrict__ bias,
                              const float* __restrict__ resid) {
    __shared__ uint32_t As[128][36];
    __shared__ uint32_t Ws[128][36];
    const int n0 = blockIdx.y * 128;
    const int j0 = blockIdx.x * 128;
    const int tid = threadIdx.x, lane = tid & 31, warp = tid >> 5;
    const int wm = (warp >> 2) * 64, wn = (warp & 3) * 32;
    float acc[4][4][4] = {};
    const int lr = tid >> 3;
    const int lc = (tid & 7) * 4;

    for (int ks = 0; ks < DMODEL / 32; ks++) {
#pragma unroll
        for (int rr = 0; rr < 128; rr += 32) {
            int n = n0 + lr + rr;
            int c = ks * 32 + lc;
            int bb = n >> 11, l = n & 2047;
            int h2 = 2 * bb + ((l >> 10) & 1);
            int l3 = (l & 1023) * 2 + (c >> 8);
            int b2 = (c >> 6) & 3;
            int d  = c & 63;
            size_t f = (size_t)h2 * 524288 + (size_t)b2 * 131072 + (size_t)l3 * 64 + d;
            float4 av = *(const float4*)&g_ao[f];
            As[lr + rr][lc + 0] = f2tf(av.x); As[lr + rr][lc + 1] = f2tf(av.y);
            As[lr + rr][lc + 2] = f2tf(av.z); As[lr + rr][lc + 3] = f2tf(av.w);
            float4 wv = *(const float4*)&W[(size_t)(j0 + lr + rr) * DMODEL + ks * 32 + lc];
            Ws[lr + rr][lc + 0] = f2tf(wv.x); Ws[lr + rr][lc + 1] = f2tf(wv.y);
            Ws[lr + rr][lc + 2] = f2tf(wv.z); Ws[lr + rr][lc + 3] = f2tf(wv.w);
        }
        __syncthreads();
#pragma unroll
        for (int k8 = 0; k8 < 4; k8++) {
            const int c0 = k8 * 8 + (lane & 3);
            uint32_t af[4][4], bf[4][2];
#pragma unroll
            for (int tm = 0; tm < 4; tm++) {
                int r0 = wm + tm * 16 + (lane >> 2);
                af[tm][0] = As[r0][c0];     af[tm][1] = As[r0 + 8][c0];
                af[tm][2] = As[r0][c0 + 4]; af[tm][3] = As[r0 + 8][c0 + 4];
            }
#pragma unroll
            for (int tn = 0; tn < 4; tn++) {
                int rn = wn + tn * 8 + (lane >> 2);
                bf[tn][0] = Ws[rn][c0]; bf[tn][1] = Ws[rn][c0 + 4];
            }
#pragma unroll
            for (int tm = 0; tm < 4; tm++)
#pragma unroll
                for (int tn = 0; tn < 4; tn++) mma8(acc[tm][tn], af[tm], bf[tn]);
        }
        __syncthreads();
    }

#pragma unroll
    for (int tm = 0; tm < 4; tm++) {
#pragma unroll
        for (int half = 0; half < 2; half++) {
            int n = n0 + wm + tm * 16 + (lane >> 2) + half * 8;
#pragma unroll
            for (int tn = 0; tn < 4; tn++) {
                int col = j0 + wn + tn * 8 + (lane & 3) * 2;
                float2 bv = *(const float2*)&bias[col];
                float2 rv = *(const float2*)&resid[(size_t)n * DMODEL + col];
                float v0 = acc[tm][tn][half * 2 + 0] + bv.x + rv.x;
                float v1 = acc[tm][tn][half * 2 + 1] + bv.y + rv.y;
                *(float2*)&g_y[(size_t)n * DMODEL + col] = make_float2(v0, v1);
            }
        }
    }
}

// -------------------- layernorm ---------------------------------------------
__global__ void ln_kernel(const float* __restrict__ gam,
                          const float* __restrict__ bet,
                          float* __restrict__ y) {
    const int n = blockIdx.x;
    const float* px = g_y + (size_t)n * DMODEL;
    const int tid = threadIdx.x;
    __shared__ float red[4];
    float v[4];
    float s = 0.f;
#pragma unroll
    for (int i = 0; i < 4; i++) { v[i] = px[tid + i * 128]; s += v[i]; }
#pragma unroll
    for (int o = 16; o > 0; o >>= 1) s += __shfl_xor_sync(0xffffffffu, s, o);
    if ((tid & 31) == 0) red[tid >> 5] = s;
    __syncthreads();
    float mu = (red[0] + red[1] + red[2] + red[3]) * (1.0f / DMODEL);
    __syncthreads();
    float vs = 0.f;
#pragma unroll
    for (int i = 0; i < 4; i++) { float d = v[i] - mu; vs += d * d; }
#pragma unroll
    for (int o = 16; o > 0; o >>= 1) vs += __shfl_xor_sync(0xffffffffu, vs, o);
    if ((tid & 31) == 0) red[tid >> 5] = vs;
    __syncthreads();
    float var = (red[0] + red[1] + red[2] + red[3]) * (1.0f / DMODEL);
    float inv = rsqrtf(var + LN_EPS);
#pragma unroll
    for (int i = 0; i < 4; i++) {
        int c = tid + i * 128;
        y[(size_t)n * DMODEL + c] = (v[i] - mu) * inv * gam[c] + bet[c];
    }
}

// ============================================================================
extern "C" void kernel_launch(void* const* d_in, const int* in_sizes, int n_in,
                              void* d_out, int out_size) {
    const float* q    = (const float*)d_in[0];
    const float* k    = (const float*)d_in[1];
    const float* v    = (const float*)d_in[2];
    const int*   mask = (const int*)d_in[3];
    const float* wq_w = (const float*)d_in[4];
    const float* wq_b = (const float*)d_in[5];
    const float* wv_w = (const float*)d_in[6];
    const float* wv_b = (const float*)d_in[7];
    const float* fc_w = (const float*)d_in[8];
    const float* fc_b = (const float*)d_in[9];
    const float* ln_g = (const float*)d_in[10];
    const float* ln_b = (const float*)d_in[11];

    float* y_out    = (float*)d_out;
    float* attn_out = (float*)d_out + (size_t)NROWS * DMODEL;

    uint32_t *p_qh16, *p_kh16;
    float *p_vh;
    cudaGetSymbolAddress((void**)&p_qh16, g_qh16);
    cudaGetSymbolAddress((void**)&p_kh16, g_kh16);
    cudaGetSymbolAddress((void**)&p_vh, g_vh);

    static bool attrs_set = false;
    if (!attrs_set) {
        cudaFuncSetAttribute(scores_mma_kernel,
                             cudaFuncAttributeMaxDynamicSharedMemorySize, 40960);
        cudaFuncSetAttribute(pv_mma_kernel,
                             cudaFuncAttributeMaxDynamicSharedMemorySize, 46080);
        attrs_set = true;
    }

    dim3 gProj(DMODEL / 128, NROWS / 128, 3);    // (4, 64, 3)
    proj_mma_kernel<<<gProj, 256>>>(q, k, v, wq_w, wq_b, wv_w, wv_b,
                                    p_qh16, p_kh16, p_vh);

    vrepack_kernel<<<(BHEADS * 1024 * 64) / 256, 256>>>();

    dim3 gScores(SEQL / 128, SEQL / 128, BATCH);  // (16, 16, 4)
    scores_mma_kernel<<<gScores, 256, 40960>>>(mask, attn_out);

    reduce_kernel<<<(BHEADS * SEQL) / 256, 256>>>();

    dim3 gPV(SEQL / 128, BHEADS);   // (16, 32)
    pv_mma_kernel<<<gPV, 256, 46080>>>(attn_out);

    dim3 gFc(DMODEL / 128, NROWS / 128);
    fc_mma_kernel<<<gFc, 256>>>(fc_w, fc_b, q);

    ln_kernel<<<NROWS, 128>>>(ln_g, ln_b, y_out);
}

// round 16
// speedup vs baseline: 1.5779x; 1.1835x over previous
#include <cuda_runtime.h>
#include <math_constants.h>
#include <cstdint>

#define BATCH 4
#define SEQL 2048
#define DMODEL 512
#define NHEAD 8
#define HDIM 64
#define BHEADS (BATCH * NHEAD)      // 32
#define NROWS (BATCH * SEQL)        // 8192
#define SCALE 0.125f                // 1/sqrt(64)
#define LN_EPS 1e-5f

// -------------------- device scratch (no allocations allowed) ----------------
__device__ uint32_t g_qh16[BHEADS * SEQL * 32];  // packed half2 pairs along dk
__device__ uint32_t g_kh16[BHEADS * SEQL * 32];
__device__ float    g_vh[BHEADS * SEQL * HDIM];  // fp32 V (head layout)
__device__ uint32_t g_vp[BHEADS * 1024 * 64];    // half2 pairs along token: [bh][kp][dv]
__device__ uint32_t g_mbits[BATCH * SEQL * 64];  // mask bitmask, word=(b*L+row)*64+w
__device__ float    g_ao[BHEADS * SEQL * HDIM];  // attention output, (B,H,L,DV) flat
__device__ float    g_y[NROWS * DMODEL];         // fc output + residual (pre-LN)
__device__ float    g_inv[BHEADS * SEQL];        // 1 / row sumexp

// -------------------- helpers ------------------------------------------------
__device__ __forceinline__ uint32_t f2tf(float x) {
    uint32_t r;
    asm("cvt.rna.tf32.f32 %0, %1;" : "=r"(r) : "f"(x));
    return r;
}

__device__ __forceinline__ uint32_t pack_h2(float lo, float hi) {
    uint32_t r;
    asm("cvt.rn.f16x2.f32 %0, %1, %2;" : "=r"(r) : "f"(hi), "f"(lo));
    return r;
}

__device__ __forceinline__ void mma8(float* c, const uint32_t* a, const uint32_t* b) {
    asm volatile(
        "mma.sync.aligned.m16n8k8.row.col.f32.tf32.tf32.f32 "
        "{%0,%1,%2,%3}, {%4,%5,%6,%7}, {%8,%9}, {%0,%1,%2,%3};\n"
        : "+f"(c[0]), "+f"(c[1]), "+f"(c[2]), "+f"(c[3])
        : "r"(a[0]), "r"(a[1]), "r"(a[2]), "r"(a[3]), "r"(b[0]), "r"(b[1]));
}

__device__ __forceinline__ void mma16(float* c, const uint32_t* a, const uint32_t* b) {
    asm volatile(
        "mma.sync.aligned.m16n8k16.row.col.f32.f16.f16.f32 "
        "{%0,%1,%2,%3}, {%4,%5,%6,%7}, {%8,%9}, {%0,%1,%2,%3};\n"
        : "+f"(c[0]), "+f"(c[1]), "+f"(c[2]), "+f"(c[3])
        : "r"(a[0]), "r"(a[1]), "r"(a[2]), "r"(a[3]), "r"(b[0]), "r"(b[1]));
}

#define CP16(dst_u32, src_ptr) \
    asm volatile("cp.async.cg.shared.global [%0], [%1], 16;\n" :: "r"(dst_u32), "l"(src_ptr))
#define CP_COMMIT() asm volatile("cp.async.commit_group;\n" ::)
#define CP_WAIT1()  asm volatile("cp.async.wait_group 1;\n" ::)
#define CP_WAIT0()  asm volatile("cp.async.wait_group 0;\n" ::)

// ============================================================================
// maskpack: mask int32 -> bitmask (bit=1 means masked)
// ============================================================================
__global__ void maskpack_kernel(const int* __restrict__ mask) {
    int gw = (blockIdx.x * 256 + threadIdx.x) >> 5;      // word id < 524288
    int lane = threadIdx.x & 31;
    int m = mask[(size_t)(gw >> 6) * SEQL + (gw & 63) * 32 + lane];
    unsigned bits = __ballot_sync(0xffffffffu, m == 1);
    if (lane == 0) g_mbits[gw] = bits;
}

// ============================================================================
// stats: per (q-tile, head) block, Q-tile resident, stream K, compute S in
// registers, accumulate sum of exp(masked S*SCALE) per row -> g_inv directly.
// 8 warps x 16 rows; 64 k-stages of 32 tokens; 2-stage cp.async for K.
// ============================================================================
__global__ __launch_bounds__(256) void stats_kernel() {
    extern __shared__ uint32_t dynsm32[];   // Q 128x36 u32 | 2 x K 32x36 u32
    const int bh = blockIdx.y, bb = bh >> 3;
    const int q0 = blockIdx.x * 128;
    const int tid = threadIdx.x, lane = tid & 31, warp = tid >> 5;
    const int wm = warp * 16;
    const int lam = lane & 3;
    const int r0 = wm + (lane >> 2);
    uint32_t* Qs = dynsm32;
    const uint32_t sbase = (uint32_t)__cvta_generic_to_shared(dynsm32);
    const uint32_t* Qg = g_qh16 + (size_t)bh * SEQL * 32;
    const uint32_t* Kg = g_kh16 + (size_t)bh * SEQL * 32;

    for (int i = tid; i < 1024; i += 256) {
        int row = i >> 3, cc = (i & 7) * 4;
        *(uint4*)&Qs[row * 36 + cc] = *(const uint4*)&Qg[(size_t)(q0 + row) * 32 + cc];
    }

    auto issue = [&](int s) {
        uint32_t kd = sbase + 18432u + (uint32_t)(s & 1) * 4608u
                    + (tid >> 3) * 144u + (tid & 7) * 16u;
        CP16(kd, Kg + (size_t)(s * 32 + (tid >> 3)) * 32 + (tid & 7) * 4);
        CP_COMMIT();
    };
    issue(0);
    issue(1);
    __syncthreads();                        // Q smem visible

    uint32_t qf[4][4];
#pragma unroll
    for (int g = 0; g < 4; g++) {
        qf[g][0] = Qs[r0 * 36 + 8 * g + lam];
        qf[g][1] = Qs[(r0 + 8) * 36 + 8 * g + lam];
        qf[g][2] = Qs[r0 * 36 + 8 * g + 4 + lam];
        qf[g][3] = Qs[(r0 + 8) * 36 + 8 * g + 4 + lam];
    }

    float rs0 = 0.f, rs1 = 0.f;
    const int sh = lam * 2;
    const uint32_t* mrow0 = g_mbits + ((size_t)bb * SEQL + q0 + r0) * 64;
    const uint32_t* mrow1 = mrow0 + 8 * 64;

    for (int s = 0; s < 64; s++) {
        if (s == 63) { CP_WAIT0(); } else { CP_WAIT1(); }
        __syncthreads();
        const uint32_t* Kb = dynsm32 + 4608 + (s & 1) * 1152;
        float accS[4][4] = {};
#pragma unroll
        for (int g = 0; g < 4; g++) {
#pragma unroll
            for (int j = 0; j < 4; j++) {
                int rn = j * 8 + (lane >> 2);
                uint32_t bf[2] = { Kb[rn * 36 + 8 * g + lam],
                                   Kb[rn * 36 + 8 * g + 4 + lam] };
                mma16(accS[j], qf[g], bf);
            }
        }
        __syncthreads();                    // buffer free
        if (s + 2 < 64) issue(s + 2);

        uint32_t mw0 = mrow0[s], mw1 = mrow1[s];
#pragma unroll
        for (int j = 0; j < 4; j++) {
            int p = j * 8 + sh;
            if (!((mw0 >> p) & 1u))       rs0 += __expf(accS[j][0] * SCALE);
            if (!((mw0 >> (p + 1)) & 1u)) rs0 += __expf(accS[j][1] * SCALE);
            if (!((mw1 >> p) & 1u))       rs1 += __expf(accS[j][2] * SCALE);
            if (!((mw1 >> (p + 1)) & 1u)) rs1 += __expf(accS[j][3] * SCALE);
        }
    }
    rs0 += __shfl_xor_sync(0xffffffffu, rs0, 1);
    rs0 += __shfl_xor_sync(0xffffffffu, rs0, 2);
    rs1 += __shfl_xor_sync(0xffffffffu, rs1, 1);
    rs1 += __shfl_xor_sync(0xffffffffu, rs1, 2);
    if (lam == 0) {
        g_inv[(size_t)bh * SEQL + q0 + r0] = 1.f / rs0;
        g_inv[(size_t)bh * SEQL + q0 + r0 + 8] = 1.f / rs1;
    }
}

// ============================================================================
// repack V: fp32 head-layout -> half2 pairs along token. [bh][kp][dv]
// ============================================================================
__global__ void vrepack_kernel() {
    int t = blockIdx.x * 256 + threadIdx.x;        // < 32*1024*64
    int n  = t & 63;
    int kp = (t >> 6) & 1023;
    int bh = t >> 16;
    size_t base = ((size_t)bh * SEQL + 2 * kp) * HDIM + n;
    g_vp[t] = pack_h2(g_vh[base], g_vh[base + HDIM]);
}

// ============================================================================
// pv: flash-style. Recompute S tile in registers from resident Q + streamed K,
// p = exp(S*SCALE)*inv (masked -> 0) in the C-fragments; store fp32 attn from
// those registers; reuse them as A-fragments for the PV mma (C layout of
// m16n8 == A layout of m16n8k16, chunk g <-> nblocks 2g,2g+1). V streamed as
// packed token-pair half2. No S materialization anywhere.
// ============================================================================
__global__ __launch_bounds__(256, 2) void pv_kernel(float* __restrict__ attn) {
    extern __shared__ uint32_t dynsm32[];   // Q 128x36 | 2 x (K 32x36 | V 16x72)
    __shared__ float sI[128];
    const int bh = blockIdx.y, bb = bh >> 3;
    const int q0 = blockIdx.x * 128;
    const int tid = threadIdx.x, lane = tid & 31, warp = tid >> 5;
    const int wm = warp * 16;
    const int lam = lane & 3;
    const int r0 = wm + (lane >> 2);
    uint32_t* Qs = dynsm32;
    const uint32_t sbase = (uint32_t)__cvta_generic_to_shared(dynsm32);
    const uint32_t* Qg = g_qh16 + (size_t)bh * SEQL * 32;
    const uint32_t* Kg = g_kh16 + (size_t)bh * SEQL * 32;
    const uint32_t* Vpg = g_vp + (size_t)bh * 1024 * 64;
    float* Ap = attn + (size_t)bh * SEQL * SEQL;

    for (int i = tid; i < 1024; i += 256) {
        int row = i >> 3, cc = (i & 7) * 4;
        *(uint4*)&Qs[row * 36 + cc] = *(const uint4*)&Qg[(size_t)(q0 + row) * 32 + cc];
    }
    if (tid < 128) sI[tid] = g_inv[(size_t)bh * SEQL + q0 + tid];

    auto issue = [&](int s) {
        uint32_t base = sbase + 18432u + (uint32_t)(s & 1) * 9216u;
        CP16(base + (tid >> 3) * 144u + (tid & 7) * 16u,
             Kg + (size_t)(s * 32 + (tid >> 3)) * 32 + (tid & 7) * 4);
        CP16(base + 4608u + (tid >> 4) * 288u + (tid & 15) * 16u,
             Vpg + (size_t)(s * 16 + (tid >> 4)) * 64 + (tid & 15) * 4);
        CP_COMMIT();
    };
    issue(0);
    issue(1);
    __syncthreads();                        // Q smem + sI visible

    uint32_t qf[4][4];
#pragma unroll
    for (int g = 0; g < 4; g++) {
        qf[g][0] = Qs[r0 * 36 + 8 * g + lam];
        qf[g][1] = Qs[(r0 + 8) * 36 + 8 * g + lam];
        qf[g][2] = Qs[r0 * 36 + 8 * g + 4 + lam];
        qf[g][3] = Qs[(r0 + 8) * 36 + 8 * g + 4 + lam];
    }
    const float I0 = sI[r0], I1 = sI[r0 + 8];

    float accO[8][4] = {};
    const int sh = lam * 2;
    const uint32_t* mrow0 = g_mbits + ((size_t)bb * SEQL + q0 + r0) * 64;
    const uint32_t* mrow1 = mrow0 + 8 * 64;
    float* arow0 = Ap + (size_t)(q0 + r0) * SEQL;
    float* arow1 = Ap + (size_t)(q0 + r0 + 8) * SEQL;

    for (int s = 0; s < 64; s++) {
        if (s == 63) { CP_WAIT0(); } else { CP_WAIT1(); }
        __syncthreads();
        const uint32_t* Kb = dynsm32 + 4608 + (s & 1) * 2304;
        const uint32_t* Vb = Kb + 1152;

        // ---- S tile in registers ----
        float accS[4][4] = {};
#pragma unroll
        for (int g = 0; g < 4; g++) {
#pragma unroll
            for (int j = 0; j < 4; j++) {
                int rn = j * 8 + (lane >> 2);
                uint32_t bf[2] = { Kb[rn * 36 + 8 * g + lam],
                                   Kb[rn * 36 + 8 * g + 4 + lam] };
                mma16(accS[j], qf[g], bf);
            }
        }

        // ---- p = exp(S*SCALE)*inv (masked->0); store final attn ----
        uint32_t mw0 = mrow0[s], mw1 = mrow1[s];
#pragma unroll
        for (int j = 0; j < 4; j++) {
            int p = j * 8 + sh;
            accS[j][0] = ((mw0 >> p) & 1u)       ? 0.f : __expf(accS[j][0] * SCALE) * I0;
            accS[j][1] = ((mw0 >> (p + 1)) & 1u) ? 0.f : __expf(accS[j][1] * SCALE) * I0;
            accS[j][2] = ((mw1 >> p) & 1u)       ? 0.f : __expf(accS[j][2] * SCALE) * I1;
            accS[j][3] = ((mw1 >> (p + 1)) & 1u) ? 0.f : __expf(accS[j][3] * SCALE) * I1;
            int col = s * 32 + j * 8 + sh;
            *(float2*)&arow0[col] = make_float2(accS[j][0], accS[j][1]);
            *(float2*)&arow1[col] = make_float2(accS[j][2], accS[j][3]);
        }

        // ---- PV mma: C-fragments reused as A-fragments ----
#pragma unroll
        for (int g = 0; g < 2; g++) {
            uint32_t af[4];
            af[0] = pack_h2(accS[2 * g][0],     accS[2 * g][1]);
            af[1] = pack_h2(accS[2 * g][2],     accS[2 * g][3]);
            af[2] = pack_h2(accS[2 * g + 1][0], accS[2 * g + 1][1]);
            af[3] = pack_h2(accS[2 * g + 1][2], accS[2 * g + 1][3]);
#pragma unroll
            for (int tn = 0; tn < 8; tn++) {
                int cn = tn * 8 + (lane >> 2);
                uint32_t bf[2] = { Vb[(g * 8 + lam) * 72 + cn],
                                   Vb[(g * 8 + lam + 4) * 72 + cn] };
                mma16(accO[tn], af, bf);
            }
        }

        __syncthreads();                    // buffer free
        if (s + 2 < 64) issue(s + 2);
    }

#pragma unroll
    for (int half = 0; half < 2; half++) {
        int row = q0 + r0 + half * 8;
#pragma unroll
        for (int tn = 0; tn < 8; tn++) {
            int col = tn * 8 + lam * 2;
            *(float2*)&g_ao[((size_t)bh * SEQL + row) * HDIM + col] =
                make_float2(accO[tn][half * 2 + 0], accO[tn][half * 2 + 1]);
        }
    }
}

// ============================================================================
// proj: all three projections in one launch (grid.z selects q/k/v).
// q/k write packed half2 (pairs along dk); v writes fp32.  tf32 mainloop.
// ============================================================================
__global__ void proj_mma_kernel(const float* __restrict__ q,
                                const float* __restrict__ k,
                                const float* __restrict__ v,
                                const float* __restrict__ wq_w,
                                const float* __restrict__ wq_b,
                                const float* __restrict__ wv_w,
                                const float* __restrict__ wv_b,
                                uint32_t* __restrict__ oq16,
                                uint32_t* __restrict__ ok16,
                                float* __restrict__ ov) {
    const int which = blockIdx.z;
    const float* A    = which == 0 ? q : (which == 1 ? k : v);
    const float* W    = which == 2 ? wv_w : wq_w;      // faithful bug: k uses wq
    const float* bias = which == 2 ? wv_b : wq_b;

    __shared__ uint32_t As[128][36];
    __shared__ uint32_t Ws[128][36];
    const int n0 = blockIdx.y * 128;
    const int j0 = blockIdx.x * 128;
    const int tid = threadIdx.x, lane = tid & 31, warp = tid >> 5;
    const int wm = (warp >> 2) * 64, wn = (warp & 3) * 32;
    float acc[4][4][4] = {};
    const int lr = tid >> 3;
    const int lc = (tid & 7) * 4;

    for (int ks = 0; ks < DMODEL / 32; ks++) {
#pragma unroll
        for (int rr = 0; rr < 128; rr += 32) {
            float4 av = *(const float4*)&A[(size_t)(n0 + lr + rr) * DMODEL + ks * 32 + lc];
            As[lr + rr][lc + 0] = f2tf(av.x); As[lr + rr][lc + 1] = f2tf(av.y);
            As[lr + rr][lc + 2] = f2tf(av.z); As[lr + rr][lc + 3] = f2tf(av.w);
            float4 wv = *(const float4*)&W[(size_t)(j0 + lr + rr) * DMODEL + ks * 32 + lc];
            Ws[lr + rr][lc + 0] = f2tf(wv.x); Ws[lr + rr][lc + 1] = f2tf(wv.y);
            Ws[lr + rr][lc + 2] = f2tf(wv.z); Ws[lr + rr][lc + 3] = f2tf(wv.w);
        }
        __syncthreads();
#pragma unroll
        for (int k8 = 0; k8 < 4; k8++) {
            const int c0 = k8 * 8 + (lane & 3);
            uint32_t af[4][4], bf[4][2];
#pragma unroll
            for (int tm = 0; tm < 4; tm++) {
                int r0 = wm + tm * 16 + (lane >> 2);
                af[tm][0] = As[r0][c0];     af[tm][1] = As[r0 + 8][c0];
                af[tm][2] = As[r0][c0 + 4]; af[tm][3] = As[r0 + 8][c0 + 4];
            }
#pragma unroll
            for (int tn = 0; tn < 4; tn++) {
                int rn = wn + tn * 8 + (lane >> 2);
                bf[tn][0] = Ws[rn][c0]; bf[tn][1] = Ws[rn][c0 + 4];
            }
#pragma unroll
            for (int tm = 0; tm < 4; tm++)
#pragma unroll
                for (int tn = 0; tn < 4; tn++) mma8(acc[tm][tn], af[tm], bf[tn]);
        }
        __syncthreads();
    }

#pragma unroll
    for (int tm = 0; tm < 4; tm++) {
#pragma unroll
        for (int half = 0; half < 2; half++) {
            int n = n0 + wm + tm * 16 + (lane >> 2) + half * 8;
            int b = n >> 11, l = n & (SEQL - 1);
#pragma unroll
            for (int tn = 0; tn < 4; tn++) {
                int col = j0 + wn + tn * 8 + (lane & 3) * 2;
                int h = col >> 6, dk = col & 63;
                float2 bv = *(const float2*)&bias[col];
                float v0 = acc[tm][tn][half * 2 + 0] + bv.x;
                float v1 = acc[tm][tn][half * 2 + 1] + bv.y;
                size_t rowbase = (size_t)(b * NHEAD + h) * SEQL + l;
                if (which == 2) {
                    *(float2*)&ov[rowbase * HDIM + dk] = make_float2(v0, v1);
                } else {
                    uint32_t* o16 = which == 0 ? oq16 : ok16;
                    o16[rowbase * 32 + (dk >> 1)] = pack_h2(v0, v1);
                }
            }
        }
    }
}

// ============================================================================
// fc: y = x @ fc_w^T + fc_b + residual, faithful .view() permutation fused.
// ============================================================================
__global__ void fc_mma_kernel(const float* __restrict__ W,
                              const float* __restrict__ bias,
                              const float* __restrict__ resid) {
    __shared__ uint32_t As[128][36];
    __shared__ uint32_t Ws[128][36];
    const int n0 = blockIdx.y * 128;
    const int j0 = blockIdx.x * 128;
    const int tid = threadIdx.x, lane = tid & 31, warp = tid >> 5;
    const int wm = (warp >> 2) * 64, wn = (warp & 3) * 32;
    float acc[4][4][4] = {};
    const int lr = tid >> 3;
    const int lc = (tid & 7) * 4;

    for (int ks = 0; ks < DMODEL / 32; ks++) {
#pragma unroll
        for (int rr = 0; rr < 128; rr += 32) {
            int n = n0 + lr + rr;
            int c = ks * 32 + lc;
            int bb = n >> 11, l = n & 2047;
            int h2 = 2 * bb + ((l >> 10) & 1);
            int l3 = (l & 1023) * 2 + (c >> 8);
            int b2 = (c >> 6) & 3;
            int d  = c & 63;
            size_t f = (size_t)h2 * 524288 + (size_t)b2 * 131072 + (size_t)l3 * 64 + d;
            float4 av = *(const float4*)&g_ao[f];
            As[lr + rr][lc + 0] = f2tf(av.x); As[lr + rr][lc + 1] = f2tf(av.y);
            As[lr + rr][lc + 2] = f2tf(av.z); As[lr + rr][lc + 3] = f2tf(av.w);
            float4 wv = *(const float4*)&W[(size_t)(j0 + lr + rr) * DMODEL + ks * 32 + lc];
            Ws[lr + rr][lc + 0] = f2tf(wv.x); Ws[lr + rr][lc + 1] = f2tf(wv.y);
            Ws[lr + rr][lc + 2] = f2tf(wv.z); Ws[lr + rr][lc + 3] = f2tf(wv.w);
        }
        __syncthreads();
#pragma unroll
        for (int k8 = 0; k8 < 4; k8++) {
            const int c0 = k8 * 8 + (lane & 3);
            uint32_t af[4][4], bf[4][2];
#pragma unroll
            for (int tm = 0; tm < 4; tm++) {
                int r0 = wm + tm * 16 + (lane >> 2);
                af[tm][0] = As[r0][c0];     af[tm][1] = As[r0 + 8][c0];
                af[tm][2] = As[r0][c0 + 4]; af[tm][3] = As[r0 + 8][c0 + 4];
            }
#pragma unroll
            for (int tn = 0; tn < 4; tn++) {
                int rn = wn + tn * 8 + (lane >> 2);
                bf[tn][0] = Ws[rn][c0]; bf[tn][1] = Ws[rn][c0 + 4];
            }
#pragma unroll
            for (int tm = 0; tm < 4; tm++)
#pragma unroll
                for (int tn = 0; tn < 4; tn++) mma8(acc[tm][tn], af[tm], bf[tn]);
        }
        __syncthreads();
    }

#pragma unroll
    for (int tm = 0; tm < 4; tm++) {
#pragma unroll
        for (int half = 0; half < 2; half++) {
            int n = n0 + wm + tm * 16 + (lane >> 2) + half * 8;
#pragma unroll
            for (int tn = 0; tn < 4; tn++) {
                int col = j0 + wn + tn * 8 + (lane & 3) * 2;
                float2 bv = *(const float2*)&bias[col];
                float2 rv = *(const float2*)&resid[(size_t)n * DMODEL + col];
                float v0 = acc[tm][tn][half * 2 + 0] + bv.x + rv.x;
                float v1 = acc[tm][tn][half * 2 + 1] + bv.y + rv.y;
                *(float2*)&g_y[(size_t)n * DMODEL + col] = make_float2(v0, v1);
            }
        }
    }
}

// -------------------- layernorm ---------------------------------------------
__global__ void ln_kernel(const float* __restrict__ gam,
                          const float* __restrict__ bet,
                          float* __restrict__ y) {
    const int n = blockIdx.x;
    const float* px = g_y + (size_t)n * DMODEL;
    const int tid = threadIdx.x;
    __shared__ float red[4];
    float v[4];
    float s = 0.f;
#pragma unroll
    for (int i = 0; i < 4; i++) { v[i] = px[tid + i * 128]; s += v[i]; }
#pragma unroll
    for (int o = 16; o > 0; o >>= 1) s += __shfl_xor_sync(0xffffffffu, s, o);
    if ((tid & 31) == 0) red[tid >> 5] = s;
    __syncthreads();
    float mu = (red[0] + red[1] + red[2] + red[3]) * (1.0f / DMODEL);
    __syncthreads();
    float vs = 0.f;
#pragma unroll
    for (int i = 0; i < 4; i++) { float d = v[i] - mu; vs += d * d; }
#pragma unroll
    for (int o = 16; o > 0; o >>= 1) vs += __shfl_xor_sync(0xffffffffu, vs, o);
    if ((tid & 31) == 0) red[tid >> 5] = vs;
    __syncthreads();
    float var = (red[0] + red[1] + red[2] + red[3]) * (1.0f / DMODEL);
    float inv = rsqrtf(var + LN_EPS);
#pragma unroll
    for (int i = 0; i < 4; i++) {
        int c = tid + i * 128;
        y[(size_t)n * DMODEL + c] = (v[i] - mu) * inv * gam[c] + bet[c];
    }
}

// ============================================================================
extern "C" void kernel_launch(void* const* d_in, const int* in_sizes, int n_in,
                              void* d_out, int out_size) {
    const float* q    = (const float*)d_in[0];
    const float* k    = (const float*)d_in[1];
    const float* v    = (const float*)d_in[2];
    const int*   mask = (const int*)d_in[3];
    const float* wq_w = (const float*)d_in[4];
    const float* wq_b = (const float*)d_in[5];
    const float* wv_w = (const float*)d_in[6];
    const float* wv_b = (const float*)d_in[7];
    const float* fc_w = (const float*)d_in[8];
    const float* fc_b = (const float*)d_in[9];
    const float* ln_g = (const float*)d_in[10];
    const float* ln_b = (const float*)d_in[11];

    float* y_out    = (float*)d_out;
    float* attn_out = (float*)d_out + (size_t)NROWS * DMODEL;

    uint32_t *p_qh16, *p_kh16;
    float *p_vh;
    cudaGetSymbolAddress((void**)&p_qh16, g_qh16);
    cudaGetSymbolAddress((void**)&p_kh16, g_kh16);
    cudaGetSymbolAddress((void**)&p_vh, g_vh);

    static bool attrs_set = false;
    if (!attrs_set) {
        cudaFuncSetAttribute(stats_kernel,
                             cudaFuncAttributeMaxDynamicSharedMemorySize, 27648);
        cudaFuncSetAttribute(pv_kernel,
                             cudaFuncAttributeMaxDynamicSharedMemorySize, 36864);
        attrs_set = true;
    }

    dim3 gProj(DMODEL / 128, NROWS / 128, 3);    // (4, 64, 3)
    proj_mma_kernel<<<gProj, 256>>>(q, k, v, wq_w, wq_b, wv_w, wv_b,
                                    p_qh16, p_kh16, p_vh);

    vrepack_kernel<<<(BHEADS * 1024 * 64) / 256, 256>>>();
    maskpack_kernel<<<(BATCH * SEQL * 64 * 32) / 256, 256>>>(mask);

    dim3 gAttn(SEQL / 128, BHEADS);   // (16, 32)
    stats_kernel<<<gAttn, 256, 27648>>>();

    pv_kernel<<<gAttn, 256, 36864>>>(attn_out);

    dim3 gFc(DMODEL / 128, NROWS / 128);
    fc_mma_kernel<<<gFc, 256>>>(fc_w, fc_b, q);

    ln_kernel<<<NROWS, 128>>>(ln_g, ln_b, y_out);
}